// round 5
// baseline (speedup 1.0000x reference)
#include <cuda_runtime.h>
#include <cuda_bf16.h>
#include <cstdint>

// ---------------- problem constants ----------------
#define NN 100000
#define EE 1600000
#define NG 512
#define D  100      // hidden dim
#define D2 200      // concat(u, r) width
#define K1 128      // input feature dim
#define SCAN_B ((NN + 255) / 256)   // 391 scan blocks

// ---------------- device scratch (static globals: allocation-free) ----------------
__device__ int   g_deg[NN];
__device__ int   g_cursor[NN];
__device__ int   g_off[NN];
__device__ int   g_part[512];
__device__ int   g_csr[EE];
__device__ float g_dinv_s[NN];
__device__ float g_dinv_n[NN];
__device__ float g_t0[(size_t)NN * D];
__device__ float g_h1[(size_t)NN * D];
__device__ float g_t1[(size_t)NN * D];
__device__ float g_h2[(size_t)NN * D];
__device__ float g_ur[(size_t)NN * D2];
__device__ float g_sum[D];
__device__ float g_sumsq[D];
__device__ float g_Wf[D * D2];
__device__ float g_bf[D2];
__device__ float g_pool[NG * D];
__device__ float g_m1[NG * 200];
__device__ float g_m2[NG * 300];
__device__ float g_m3[NG * 200];

// ---------------- packed fp32 helpers (sm_103a f32x2) ----------------
__device__ __forceinline__ unsigned long long pack2(float a, float b) {
    unsigned long long r;
    asm("mov.b64 %0, {%1, %2};" : "=l"(r) : "f"(a), "f"(b));
    return r;
}
__device__ __forceinline__ void fma2(unsigned long long& d, unsigned long long a,
                                     unsigned long long b) {
    asm("fma.rn.f32x2 %0, %1, %2, %0;" : "+l"(d) : "l"(a), "l"(b));
}
__device__ __forceinline__ void unpack2(unsigned long long v, float& lo, float& hi) {
    asm("mov.b64 {%0, %1}, %2;" : "=f"(lo), "=f"(hi) : "l"(v));
}

// ---------------- small helper kernels ----------------
__global__ void zero_kernel() {
    int i = blockIdx.x * blockDim.x + threadIdx.x;
    int stride = gridDim.x * blockDim.x;
    for (int k = i; k < NN; k += stride) { g_deg[k] = 0; g_cursor[k] = 0; }
    for (int k = i; k < NG * D; k += stride) g_pool[k] = 0.f;
    if (i < D) { g_sum[i] = 0.f; g_sumsq[i] = 0.f; }
}

__global__ void deg_kernel(const int* __restrict__ dst) {
    int e = blockIdx.x * blockDim.x + threadIdx.x;
    if (e < EE) atomicAdd(&g_deg[dst[e]], 1);
}

// two-level exclusive scan of g_deg into g_off
__global__ void scan1_kernel() {
    __shared__ int sh[256];
    int tid = threadIdx.x;
    int i = blockIdx.x * 256 + tid;
    int v = (i < NN) ? g_deg[i] : 0;
    sh[tid] = v;
    __syncthreads();
    for (int ofs = 1; ofs < 256; ofs <<= 1) {
        int t = (tid >= ofs) ? sh[tid - ofs] : 0;
        __syncthreads();
        sh[tid] += t;
        __syncthreads();
    }
    if (i < NN) g_off[i] = sh[tid] - v;
    if (tid == 255) g_part[blockIdx.x] = sh[255];
}

__global__ void scan2_kernel() {
    __shared__ int sh[512];
    int tid = threadIdx.x;
    int v = (tid < SCAN_B) ? g_part[tid] : 0;
    sh[tid] = v;
    __syncthreads();
    for (int ofs = 1; ofs < 512; ofs <<= 1) {
        int t = (tid >= ofs) ? sh[tid - ofs] : 0;
        __syncthreads();
        sh[tid] += t;
        __syncthreads();
    }
    g_part[tid] = sh[tid] - v;
}

// scan finalize + dinv computation (fused)
__global__ void scan3_kernel() {
    int i = blockIdx.x * blockDim.x + threadIdx.x;
    if (i < NN) {
        g_off[i] += g_part[i >> 8];
        int d = g_deg[i];
        g_dinv_s[i] = rsqrtf((float)(d + 1));
        g_dinv_n[i] = (d > 0) ? rsqrtf((float)d) : 0.f;
    }
}

__global__ void csrfill_kernel(const int* __restrict__ src, const int* __restrict__ dst) {
    int e = blockIdx.x * blockDim.x + threadIdx.x;
    if (e < EE) {
        int d = dst[e];
        int pos = g_off[d] + atomicAdd(&g_cursor[d], 1);
        g_csr[pos] = src[e];
    }
}

// ---------------- node-level GEMM with packed f32x2 FMAs ----------------
// C[n x NC] = A[n x K] @ W[K x NC] (+bias).
// 256 threads as 16x16 (tx=col group, ty=row group). Each thread: RP row-PAIRS
// (2*RP rows) x CT cols. Row pairs packed in b64; W duplicated (w,w) in smem.
template <int K, int KC, int NC, int RP>
__global__ void gemm_nodes(const float* __restrict__ A, const float* __restrict__ W,
                           const float* __restrict__ bias, float* __restrict__ C) {
    constexpr int ROWS = 32 * RP;          // 16 groups * 2*RP rows
    constexpr int CT = (NC + 15) / 16;
    constexpr int CTP = CT * 16;
    constexpr int XP = ROWS + 4;           // even -> 8B-aligned row pairs
    __shared__ unsigned long long Ws[KC * CTP];   // (w, w) duplicated
    __shared__ __align__(16) float Xs[KC * XP];   // transposed X tile
    int tid = threadIdx.x;
    int rowbase = blockIdx.x * ROWS;
    int tx = tid & 15, ty = tid >> 4;

    unsigned long long acc[RP][CT];
#pragma unroll
    for (int i = 0; i < RP; i++)
#pragma unroll
        for (int j = 0; j < CT; j++) acc[i][j] = 0ull;

    for (int k0 = 0; k0 < K; k0 += KC) {
        for (int idx = tid; idx < KC * CTP; idx += 256) {
            int k = idx / CTP, c = idx % CTP;
            float w = (c < NC) ? W[(k0 + k) * NC + c] : 0.f;
            Ws[idx] = pack2(w, w);
        }
        for (int idx = tid; idx < ROWS * KC; idx += 256) {
            int r = idx / KC, k = idx % KC;
            int gr = rowbase + r;
            Xs[k * XP + r] = (gr < NN) ? A[(size_t)gr * K + k0 + k] : 0.f;
        }
        __syncthreads();

#pragma unroll 2
        for (int k = 0; k < KC; k++) {
            unsigned long long xp[RP];
            const unsigned long long* xrow =
                (const unsigned long long*)&Xs[k * XP + ty * (2 * RP)];
#pragma unroll
            for (int i = 0; i < RP; i++) xp[i] = xrow[i];
#pragma unroll
            for (int j = 0; j < CT; j++) {
                unsigned long long wp = Ws[k * CTP + tx + j * 16];
#pragma unroll
                for (int i = 0; i < RP; i++) fma2(acc[i][j], xp[i], wp);
            }
        }
        __syncthreads();
    }

#pragma unroll
    for (int i = 0; i < RP; i++) {
        int gr0 = rowbase + ty * (2 * RP) + 2 * i;
#pragma unroll
        for (int j = 0; j < CT; j++) {
            int c = tx + j * 16;
            if (c >= NC) continue;
            float v0, v1;
            unpack2(acc[i][j], v0, v1);
            float bb = bias ? bias[c] : 0.f;
            if (gr0 < NN)     C[(size_t)gr0 * NC + c]       = v0 + bb;
            if (gr0 + 1 < NN) C[(size_t)(gr0 + 1) * NC + c] = v1 + bb;
        }
    }
}

// ---------------- GCN propagation with self loops: warp/node, float4, uniform idx ----------------
__global__ void prop_self_kernel(const float* __restrict__ T, const float* __restrict__ bias,
                                 float* __restrict__ out) {
    int node = blockIdx.x * 8 + (threadIdx.x >> 5);
    if (node >= NN) return;
    int lane = threadIdx.x & 31;
    int start = g_off[node];
    int cnt = g_deg[node];
    float di = g_dinv_s[node];
    bool act = lane < 25;
    int col = lane * 4;
    float4 a = make_float4(0.f, 0.f, 0.f, 0.f);

    int e = 0;
    for (; e + 2 <= cnt; e += 2) {
        int j0 = g_csr[start + e];          // uniform broadcast loads
        int j1 = g_csr[start + e + 1];
        float w0 = g_dinv_s[j0];
        float w1 = g_dinv_s[j1];
        if (act) {
            const float4 v0 = *(const float4*)(T + (size_t)j0 * D + col);
            const float4 v1 = *(const float4*)(T + (size_t)j1 * D + col);
            a.x = fmaf(w0, v0.x, a.x); a.y = fmaf(w0, v0.y, a.y);
            a.z = fmaf(w0, v0.z, a.z); a.w = fmaf(w0, v0.w, a.w);
            a.x = fmaf(w1, v1.x, a.x); a.y = fmaf(w1, v1.y, a.y);
            a.z = fmaf(w1, v1.z, a.z); a.w = fmaf(w1, v1.w, a.w);
        }
    }
    if (e < cnt) {
        int j = g_csr[start + e];
        float w = g_dinv_s[j];
        if (act) {
            const float4 v = *(const float4*)(T + (size_t)j * D + col);
            a.x = fmaf(w, v.x, a.x); a.y = fmaf(w, v.y, a.y);
            a.z = fmaf(w, v.z, a.z); a.w = fmaf(w, v.w, a.w);
        }
    }
    if (act) {
        const float4 v = *(const float4*)(T + (size_t)node * D + col);
        a.x = fmaf(di, v.x, a.x); a.y = fmaf(di, v.y, a.y);
        a.z = fmaf(di, v.z, a.z); a.w = fmaf(di, v.w, a.w);
        const float4 bb = *(const float4*)(bias + col);
        float4 o;
        o.x = fmaxf(fmaf(di, a.x, bb.x), 0.f);
        o.y = fmaxf(fmaf(di, a.y, bb.y), 0.f);
        o.z = fmaxf(fmaf(di, a.z, bb.z), 0.f);
        o.w = fmaxf(fmaf(di, a.w, bb.w), 0.f);
        *(float4*)(out + (size_t)node * D + col) = o;
    }
}

// ---------------- BatchNorm stats: register-column reduction, 1 atomic/block/col ----------------
__global__ void bn_stats_kernel() {
    int c = threadIdx.x;           // 128 threads, first 100 active
    if (c >= D) return;
    int r0 = blockIdx.x * 256;
    int r1 = min(r0 + 256, NN);
    float s = 0.f, q = 0.f;
    for (int r = r0; r < r1; r++) {
        float v = g_h2[(size_t)r * D + c];
        s += v;
        q = fmaf(v, v, q);
    }
    atomicAdd(&g_sum[c], s);
    atomicAdd(&g_sumsq[c], q);
}

// ---------------- fold BatchNorm affine into ARMA weights ----------------
// h = h2*s + t  =>  h@Wa = h2@(diag(s)Wa) + t@Wa
__global__ void fold_kernel(const float* __restrict__ gamma, const float* __restrict__ beta,
                            const float* __restrict__ Wa_init, const float* __restrict__ Wa_root,
                            const float* __restrict__ ba) {
    __shared__ float s[D], t[D];
    int tid = threadIdx.x;
    if (tid < D) {
        float mu = g_sum[tid] * (1.f / NN);
        float var = g_sumsq[tid] * (1.f / NN) - mu * mu;
        float rs = rsqrtf(var + 1e-5f);
        float sv = gamma[tid] * rs;
        s[tid] = sv;
        t[tid] = beta[tid] - mu * sv;
    }
    __syncthreads();
    for (int idx = tid; idx < D * D2; idx += blockDim.x) {
        int k = idx / D2, c = idx % D2;
        float w = (c < D) ? Wa_init[k * D + c] : Wa_root[k * D + (c - D)];
        g_Wf[idx] = s[k] * w;
    }
    for (int c = tid; c < D2; c += blockDim.x) {
        float acc;
        if (c < D) {
            acc = 0.f;
            for (int k = 0; k < D; k++) acc = fmaf(t[k], Wa_init[k * D + c], acc);
        } else {
            int cc = c - D;
            acc = ba[cc];
            for (int k = 0; k < D; k++) acc = fmaf(t[k], Wa_root[k * D + cc], acc);
        }
        g_bf[c] = acc;
    }
}

// ---------------- ARMA prop (no self loops) + root add + relu + pooled scatter ----------------
__global__ void arma_pool_kernel(const int* __restrict__ batch) {
    int node = blockIdx.x * 8 + (threadIdx.x >> 5);
    if (node >= NN) return;
    int lane = threadIdx.x & 31;
    int start = g_off[node];
    int cnt = g_deg[node];
    float di = g_dinv_n[node];
    bool act = lane < 25;
    int col = lane * 4;
    float4 a = make_float4(0.f, 0.f, 0.f, 0.f);

    int e = 0;
    for (; e + 2 <= cnt; e += 2) {
        int j0 = g_csr[start + e];
        int j1 = g_csr[start + e + 1];
        float w0 = g_dinv_n[j0];
        float w1 = g_dinv_n[j1];
        if (act) {
            const float4 v0 = *(const float4*)(g_ur + (size_t)j0 * D2 + col);
            const float4 v1 = *(const float4*)(g_ur + (size_t)j1 * D2 + col);
            a.x = fmaf(w0, v0.x, a.x); a.y = fmaf(w0, v0.y, a.y);
            a.z = fmaf(w0, v0.z, a.z); a.w = fmaf(w0, v0.w, a.w);
            a.x = fmaf(w1, v1.x, a.x); a.y = fmaf(w1, v1.y, a.y);
            a.z = fmaf(w1, v1.z, a.z); a.w = fmaf(w1, v1.w, a.w);
        }
    }
    if (e < cnt) {
        int j = g_csr[start + e];
        float w = g_dinv_n[j];
        if (act) {
            const float4 v = *(const float4*)(g_ur + (size_t)j * D2 + col);
            a.x = fmaf(w, v.x, a.x); a.y = fmaf(w, v.y, a.y);
            a.z = fmaf(w, v.z, a.z); a.w = fmaf(w, v.w, a.w);
        }
    }
    if (act) {
        const float4 r = *(const float4*)(g_ur + (size_t)node * D2 + D + col);
        float v0 = fmaxf(fmaf(di, a.x, r.x), 0.f);
        float v1 = fmaxf(fmaf(di, a.y, r.y), 0.f);
        float v2 = fmaxf(fmaf(di, a.z, r.z), 0.f);
        float v3 = fmaxf(fmaf(di, a.w, r.w), 0.f);
        float* p = g_pool + (size_t)batch[node] * D + col;
        atomicAdd(&p[0], v0);
        atomicAdd(&p[1], v1);
        atomicAdd(&p[2], v2);
        atomicAdd(&p[3], v3);
    }
}

// ---------------- small MLP GEMM (row per block) ----------------
template <int K, int NC, bool RELU>
__global__ void mlp_gemm(const float* __restrict__ A, const float* __restrict__ W,
                         const float* __restrict__ b, float* __restrict__ C) {
    __shared__ float As[K];
    int r = blockIdx.x;
    for (int k = threadIdx.x; k < K; k += blockDim.x) As[k] = A[r * K + k];
    __syncthreads();
    for (int c = threadIdx.x; c < NC; c += blockDim.x) {
        float acc = b[c];
#pragma unroll 4
        for (int k = 0; k < K; k++) acc = fmaf(As[k], W[k * NC + c], acc);
        C[r * NC + c] = RELU ? fmaxf(acc, 0.f) : acc;
    }
}

// ---------------- host helper: real device address of a __device__ symbol ----------------
static float* symaddr(const void* sym) {
    void* p = nullptr;
    cudaGetSymbolAddress(&p, sym);
    return (float*)p;
}

// ---------------- launcher ----------------
extern "C" void kernel_launch(void* const* d_in, const int* in_sizes, int n_in,
                              void* d_out, int out_size) {
    const float* x       = (const float*)d_in[0];
    const int*   src     = (const int*)d_in[1];
    const int*   dst     = (const int*)d_in[2];
    const int*   batch   = (const int*)d_in[3];
    const float* W1      = (const float*)d_in[4];
    const float* b1      = (const float*)d_in[5];
    const float* W2      = (const float*)d_in[6];
    const float* b2      = (const float*)d_in[7];
    const float* gamma   = (const float*)d_in[8];
    const float* beta    = (const float*)d_in[9];
    const float* Wa_init = (const float*)d_in[10];
    const float* Wa_root = (const float*)d_in[11];
    const float* ba      = (const float*)d_in[12];
    const float* Wf1     = (const float*)d_in[13];
    const float* bf1     = (const float*)d_in[14];
    const float* Wf2     = (const float*)d_in[15];
    const float* bf2     = (const float*)d_in[16];
    const float* Wf3     = (const float*)d_in[17];
    const float* bf3     = (const float*)d_in[18];
    const float* Wf4     = (const float*)d_in[19];
    const float* bf4     = (const float*)d_in[20];
    float* out = (float*)d_out;

    // real device addresses of the scratch buffers (NOT the host shadows!)
    float* p_t0   = symaddr(g_t0);
    float* p_h1   = symaddr(g_h1);
    float* p_t1   = symaddr(g_t1);
    float* p_h2   = symaddr(g_h2);
    float* p_ur   = symaddr(g_ur);
    float* p_Wf   = symaddr(g_Wf);
    float* p_bf   = symaddr(g_bf);
    float* p_pool = symaddr(g_pool);
    float* p_m1   = symaddr(g_m1);
    float* p_m2   = symaddr(g_m2);
    float* p_m3   = symaddr(g_m3);

    const int GB_N = (NN + 255) / 256;       // 391
    const int GB_E = (EE + 255) / 256;       // 6250
    const int GB_P = (NN + 7) / 8;           // 12500 (warp per node, 8/block)

    zero_kernel<<<GB_N, 256>>>();
    deg_kernel<<<GB_E, 256>>>(dst);
    scan1_kernel<<<SCAN_B, 256>>>();
    scan2_kernel<<<1, 512>>>();
    scan3_kernel<<<GB_N, 256>>>();
    csrfill_kernel<<<GB_E, 256>>>(src, dst);

    // SGConv 1: t0 = x @ W1 ; h1 = relu(prop_self(t0) + b1)
    gemm_nodes<K1, 32, D, 4><<<(NN + 127) / 128, 256>>>(x, W1, nullptr, p_t0);
    prop_self_kernel<<<GB_P, 256>>>(p_t0, b1, p_h1);

    // SGConv 2: t1 = h1 @ W2 ; h2 = relu(prop_self(t1) + b2)
    gemm_nodes<D, 25, D, 4><<<(NN + 127) / 128, 256>>>(p_h1, W2, nullptr, p_t1);
    prop_self_kernel<<<GB_P, 256>>>(p_t1, b2, p_h2);

    // BatchNorm stats + fold into ARMA weights
    bn_stats_kernel<<<GB_N, 128>>>();
    fold_kernel<<<1, 256>>>(gamma, beta, Wa_init, Wa_root, ba);

    // ARMA: ur = h2 @ Wf + bf  (u = cols 0..99, r = cols 100..199)
    gemm_nodes<D, 20, D2, 2><<<(NN + 63) / 64, 256>>>(p_h2, p_Wf, p_bf, p_ur);

    // a = relu(prop_noself(u) + r), pooled by graph id (fused)
    arma_pool_kernel<<<GB_P, 256>>>(batch);

    // MLP head on [512, 100]
    mlp_gemm<100, 200, true><<<NG, 256>>>(p_pool, Wf1, bf1, p_m1);
    mlp_gemm<200, 300, true><<<NG, 256>>>(p_m1, Wf2, bf2, p_m2);
    mlp_gemm<300, 200, true><<<NG, 256>>>(p_m2, Wf3, bf3, p_m3);
    mlp_gemm<200, 1, false><<<NG, 32>>>(p_m3, Wf4, bf4, out);
}

// round 6
// speedup vs baseline: 1.1224x; 1.1224x over previous
#include <cuda_runtime.h>
#include <cuda_bf16.h>
#include <cstdint>

// ---------------- problem constants ----------------
#define NN 100000
#define EE 1600000
#define NG 512
#define D  100      // hidden dim
#define D2 200      // concat(u, r) width
#define K1 128      // input feature dim
#define SCAN_B ((NN + 255) / 256)   // 391 scan blocks

// ---------------- device scratch (static globals: allocation-free) ----------------
__device__ int   g_deg[NN];
__device__ int   g_cursor[NN];
__device__ int   g_off[NN];
__device__ int   g_part[512];
__device__ int   g_csr[EE];
__device__ float g_dinv_s[NN];
__device__ float g_dinv_n[NN];
__device__ float g_t0[(size_t)NN * D];
__device__ float g_h1[(size_t)NN * D];
__device__ float g_t1[(size_t)NN * D];
__device__ float g_h2[(size_t)NN * D];
__device__ float g_ur[(size_t)NN * D2];
__device__ float g_sum[D];
__device__ float g_sumsq[D];
__device__ float g_Wf[D * D2];
__device__ float g_bf[D2];
__device__ float g_pool[NG * D];
__device__ float g_m1[NG * 200];
__device__ float g_m2[NG * 300];
__device__ float g_m3[NG * 200];

// ---------------- small helper kernels ----------------
__global__ void zero_kernel() {
    int i = blockIdx.x * blockDim.x + threadIdx.x;
    int stride = gridDim.x * blockDim.x;
    for (int k = i; k < NN; k += stride) { g_deg[k] = 0; g_cursor[k] = 0; }
    for (int k = i; k < NG * D; k += stride) g_pool[k] = 0.f;
    if (i < D) { g_sum[i] = 0.f; g_sumsq[i] = 0.f; }
}

__global__ void deg_kernel(const int* __restrict__ dst) {
    int e = blockIdx.x * blockDim.x + threadIdx.x;
    if (e < EE) atomicAdd(&g_deg[dst[e]], 1);
}

// two-level exclusive scan of g_deg into g_off
__global__ void scan1_kernel() {
    __shared__ int sh[256];
    int tid = threadIdx.x;
    int i = blockIdx.x * 256 + tid;
    int v = (i < NN) ? g_deg[i] : 0;
    sh[tid] = v;
    __syncthreads();
    for (int ofs = 1; ofs < 256; ofs <<= 1) {
        int t = (tid >= ofs) ? sh[tid - ofs] : 0;
        __syncthreads();
        sh[tid] += t;
        __syncthreads();
    }
    if (i < NN) g_off[i] = sh[tid] - v;
    if (tid == 255) g_part[blockIdx.x] = sh[255];
}

__global__ void scan2_kernel() {
    __shared__ int sh[512];
    int tid = threadIdx.x;
    int v = (tid < SCAN_B) ? g_part[tid] : 0;
    sh[tid] = v;
    __syncthreads();
    for (int ofs = 1; ofs < 512; ofs <<= 1) {
        int t = (tid >= ofs) ? sh[tid - ofs] : 0;
        __syncthreads();
        sh[tid] += t;
        __syncthreads();
    }
    g_part[tid] = sh[tid] - v;
}

// scan finalize + dinv computation (fused)
__global__ void scan3_kernel() {
    int i = blockIdx.x * blockDim.x + threadIdx.x;
    if (i < NN) {
        g_off[i] += g_part[i >> 8];
        int d = g_deg[i];
        g_dinv_s[i] = rsqrtf((float)(d + 1));
        g_dinv_n[i] = (d > 0) ? rsqrtf((float)d) : 0.f;
    }
}

__global__ void csrfill_kernel(const int* __restrict__ src, const int* __restrict__ dst) {
    int e = blockIdx.x * blockDim.x + threadIdx.x;
    if (e < EE) {
        int d = dst[e];
        int pos = g_off[d] + atomicAdd(&g_cursor[d], 1);
        g_csr[pos] = src[e];
    }
}

// ---------------- node-level GEMM (R3 scalar version, best known) ----------------
// C[n x NC] = A[n x K] @ W[K x NC] (+bias); K-chunked, static shared <= 48KB.
template <int K, int KC, int NC>
__global__ void gemm_nodes(const float* __restrict__ A, const float* __restrict__ W,
                           const float* __restrict__ bias, float* __restrict__ C) {
    constexpr int ROWS = 64;
    constexpr int CT = (NC + 15) / 16;
    constexpr int CTP = CT * 16;
    __shared__ float Ws[KC * CTP];
    __shared__ float Xs[ROWS * (KC + 1)];
    int tid = threadIdx.x;
    int rowbase = blockIdx.x * ROWS;
    int tx = tid & 15, ty = tid >> 4;   // ty: 0..15 -> 4 rows each

    float acc[4][CT];
#pragma unroll
    for (int i = 0; i < 4; i++)
#pragma unroll
        for (int j = 0; j < CT; j++) acc[i][j] = 0.f;

    for (int k0 = 0; k0 < K; k0 += KC) {
        for (int idx = tid; idx < KC * CTP; idx += 256) {
            int k = idx / CTP, c = idx % CTP;
            Ws[idx] = (c < NC) ? W[(k0 + k) * NC + c] : 0.f;
        }
        for (int idx = tid; idx < ROWS * KC; idx += 256) {
            int r = idx / KC, k = idx % KC;
            int gr = rowbase + r;
            Xs[r * (KC + 1) + k] = (gr < NN) ? A[(size_t)gr * K + k0 + k] : 0.f;
        }
        __syncthreads();

#pragma unroll 2
        for (int k = 0; k < KC; k++) {
            float a[4];
#pragma unroll
            for (int i = 0; i < 4; i++) a[i] = Xs[(ty * 4 + i) * (KC + 1) + k];
#pragma unroll
            for (int j = 0; j < CT; j++) {
                float w = Ws[k * CTP + tx + j * 16];
#pragma unroll
                for (int i = 0; i < 4; i++) acc[i][j] = fmaf(a[i], w, acc[i][j]);
            }
        }
        __syncthreads();
    }

#pragma unroll
    for (int i = 0; i < 4; i++) {
        int gr = rowbase + ty * 4 + i;
        if (gr >= NN) continue;
#pragma unroll
        for (int j = 0; j < CT; j++) {
            int c = tx + j * 16;
            if (c < NC) {
                float v = acc[i][j];
                if (bias) v += bias[c];
                C[(size_t)gr * NC + c] = v;
            }
        }
    }
}

// ---------------- GCN prop with self loops: warp/node, float4, uniform idx, unroll 4 ----------------
__global__ void prop_self_kernel(const float* __restrict__ T, const float* __restrict__ bias,
                                 float* __restrict__ out) {
    int node = blockIdx.x * 8 + (threadIdx.x >> 5);
    if (node >= NN) return;
    int lane = threadIdx.x & 31;
    int start = g_off[node];
    int cnt = g_deg[node];
    float di = g_dinv_s[node];
    bool act = lane < 25;
    int col = lane * 4;
    float4 a = make_float4(0.f, 0.f, 0.f, 0.f);

    int e = 0;
    for (; e + 4 <= cnt; e += 4) {
        int j0 = g_csr[start + e];
        int j1 = g_csr[start + e + 1];
        int j2 = g_csr[start + e + 2];
        int j3 = g_csr[start + e + 3];
        float w0 = g_dinv_s[j0], w1 = g_dinv_s[j1];
        float w2 = g_dinv_s[j2], w3 = g_dinv_s[j3];
        if (act) {
            const float4 v0 = *(const float4*)(T + (size_t)j0 * D + col);
            const float4 v1 = *(const float4*)(T + (size_t)j1 * D + col);
            const float4 v2 = *(const float4*)(T + (size_t)j2 * D + col);
            const float4 v3 = *(const float4*)(T + (size_t)j3 * D + col);
            a.x = fmaf(w0, v0.x, a.x); a.y = fmaf(w0, v0.y, a.y);
            a.z = fmaf(w0, v0.z, a.z); a.w = fmaf(w0, v0.w, a.w);
            a.x = fmaf(w1, v1.x, a.x); a.y = fmaf(w1, v1.y, a.y);
            a.z = fmaf(w1, v1.z, a.z); a.w = fmaf(w1, v1.w, a.w);
            a.x = fmaf(w2, v2.x, a.x); a.y = fmaf(w2, v2.y, a.y);
            a.z = fmaf(w2, v2.z, a.z); a.w = fmaf(w2, v2.w, a.w);
            a.x = fmaf(w3, v3.x, a.x); a.y = fmaf(w3, v3.y, a.y);
            a.z = fmaf(w3, v3.z, a.z); a.w = fmaf(w3, v3.w, a.w);
        }
    }
    for (; e < cnt; e++) {
        int j = g_csr[start + e];
        float w = g_dinv_s[j];
        if (act) {
            const float4 v = *(const float4*)(T + (size_t)j * D + col);
            a.x = fmaf(w, v.x, a.x); a.y = fmaf(w, v.y, a.y);
            a.z = fmaf(w, v.z, a.z); a.w = fmaf(w, v.w, a.w);
        }
    }
    if (act) {
        const float4 v = *(const float4*)(T + (size_t)node * D + col);
        a.x = fmaf(di, v.x, a.x); a.y = fmaf(di, v.y, a.y);
        a.z = fmaf(di, v.z, a.z); a.w = fmaf(di, v.w, a.w);
        const float4 bb = *(const float4*)(bias + col);
        float4 o;
        o.x = fmaxf(fmaf(di, a.x, bb.x), 0.f);
        o.y = fmaxf(fmaf(di, a.y, bb.y), 0.f);
        o.z = fmaxf(fmaf(di, a.z, bb.z), 0.f);
        o.w = fmaxf(fmaf(di, a.w, bb.w), 0.f);
        *(float4*)(out + (size_t)node * D + col) = o;
    }
}

// ---------------- BatchNorm stats: register-column reduction, 1 atomic/block/col ----------------
__global__ void bn_stats_kernel() {
    int c = threadIdx.x;           // 128 threads, first 100 active
    if (c >= D) return;
    int r0 = blockIdx.x * 256;
    int r1 = min(r0 + 256, NN);
    float s = 0.f, q = 0.f;
    for (int r = r0; r < r1; r++) {
        float v = g_h2[(size_t)r * D + c];
        s += v;
        q = fmaf(v, v, q);
    }
    atomicAdd(&g_sum[c], s);
    atomicAdd(&g_sumsq[c], q);
}

// ---------------- fold BatchNorm affine into ARMA weights ----------------
// h = h2*s + t  =>  h@Wa = h2@(diag(s)Wa) + t@Wa
__global__ void fold_kernel(const float* __restrict__ gamma, const float* __restrict__ beta,
                            const float* __restrict__ Wa_init, const float* __restrict__ Wa_root,
                            const float* __restrict__ ba) {
    __shared__ float s[D], t[D];
    int tid = threadIdx.x;
    if (tid < D) {
        float mu = g_sum[tid] * (1.f / NN);
        float var = g_sumsq[tid] * (1.f / NN) - mu * mu;
        float rs = rsqrtf(var + 1e-5f);
        float sv = gamma[tid] * rs;
        s[tid] = sv;
        t[tid] = beta[tid] - mu * sv;
    }
    __syncthreads();
    for (int idx = tid; idx < D * D2; idx += blockDim.x) {
        int k = idx / D2, c = idx % D2;
        float w = (c < D) ? Wa_init[k * D + c] : Wa_root[k * D + (c - D)];
        g_Wf[idx] = s[k] * w;
    }
    for (int c = tid; c < D2; c += blockDim.x) {
        float acc;
        if (c < D) {
            acc = 0.f;
            for (int k = 0; k < D; k++) acc = fmaf(t[k], Wa_init[k * D + c], acc);
        } else {
            int cc = c - D;
            acc = ba[cc];
            for (int k = 0; k < D; k++) acc = fmaf(t[k], Wa_root[k * D + cc], acc);
        }
        g_bf[c] = acc;
    }
}

// ---------------- ARMA prop (no self loops) + root add + relu + pooled scatter ----------------
__global__ void arma_pool_kernel(const int* __restrict__ batch) {
    int node = blockIdx.x * 8 + (threadIdx.x >> 5);
    if (node >= NN) return;
    int lane = threadIdx.x & 31;
    int start = g_off[node];
    int cnt = g_deg[node];
    float di = g_dinv_n[node];
    bool act = lane < 25;
    int col = lane * 4;
    float4 a = make_float4(0.f, 0.f, 0.f, 0.f);

    int e = 0;
    for (; e + 4 <= cnt; e += 4) {
        int j0 = g_csr[start + e];
        int j1 = g_csr[start + e + 1];
        int j2 = g_csr[start + e + 2];
        int j3 = g_csr[start + e + 3];
        float w0 = g_dinv_n[j0], w1 = g_dinv_n[j1];
        float w2 = g_dinv_n[j2], w3 = g_dinv_n[j3];
        if (act) {
            const float4 v0 = *(const float4*)(g_ur + (size_t)j0 * D2 + col);
            const float4 v1 = *(const float4*)(g_ur + (size_t)j1 * D2 + col);
            const float4 v2 = *(const float4*)(g_ur + (size_t)j2 * D2 + col);
            const float4 v3 = *(const float4*)(g_ur + (size_t)j3 * D2 + col);
            a.x = fmaf(w0, v0.x, a.x); a.y = fmaf(w0, v0.y, a.y);
            a.z = fmaf(w0, v0.z, a.z); a.w = fmaf(w0, v0.w, a.w);
            a.x = fmaf(w1, v1.x, a.x); a.y = fmaf(w1, v1.y, a.y);
            a.z = fmaf(w1, v1.z, a.z); a.w = fmaf(w1, v1.w, a.w);
            a.x = fmaf(w2, v2.x, a.x); a.y = fmaf(w2, v2.y, a.y);
            a.z = fmaf(w2, v2.z, a.z); a.w = fmaf(w2, v2.w, a.w);
            a.x = fmaf(w3, v3.x, a.x); a.y = fmaf(w3, v3.y, a.y);
            a.z = fmaf(w3, v3.z, a.z); a.w = fmaf(w3, v3.w, a.w);
        }
    }
    for (; e < cnt; e++) {
        int j = g_csr[start + e];
        float w = g_dinv_n[j];
        if (act) {
            const float4 v = *(const float4*)(g_ur + (size_t)j * D2 + col);
            a.x = fmaf(w, v.x, a.x); a.y = fmaf(w, v.y, a.y);
            a.z = fmaf(w, v.z, a.z); a.w = fmaf(w, v.w, a.w);
        }
    }
    if (act) {
        const float4 r = *(const float4*)(g_ur + (size_t)node * D2 + D + col);
        float v0 = fmaxf(fmaf(di, a.x, r.x), 0.f);
        float v1 = fmaxf(fmaf(di, a.y, r.y), 0.f);
        float v2 = fmaxf(fmaf(di, a.z, r.z), 0.f);
        float v3 = fmaxf(fmaf(di, a.w, r.w), 0.f);
        float* p = g_pool + (size_t)batch[node] * D + col;
        atomicAdd(&p[0], v0);
        atomicAdd(&p[1], v1);
        atomicAdd(&p[2], v2);
        atomicAdd(&p[3], v3);
    }
}

// ---------------- small MLP GEMM (row per block) ----------------
template <int K, int NC, bool RELU>
__global__ void mlp_gemm(const float* __restrict__ A, const float* __restrict__ W,
                         const float* __restrict__ b, float* __restrict__ C) {
    __shared__ float As[K];
    int r = blockIdx.x;
    for (int k = threadIdx.x; k < K; k += blockDim.x) As[k] = A[r * K + k];
    __syncthreads();
    for (int c = threadIdx.x; c < NC; c += blockDim.x) {
        float acc = b[c];
#pragma unroll 4
        for (int k = 0; k < K; k++) acc = fmaf(As[k], W[k * NC + c], acc);
        C[r * NC + c] = RELU ? fmaxf(acc, 0.f) : acc;
    }
}

// ---------------- host helper: real device address of a __device__ symbol ----------------
static float* symaddr(const void* sym) {
    void* p = nullptr;
    cudaGetSymbolAddress(&p, sym);
    return (float*)p;
}

// ---------------- launcher ----------------
extern "C" void kernel_launch(void* const* d_in, const int* in_sizes, int n_in,
                              void* d_out, int out_size) {
    const float* x       = (const float*)d_in[0];
    const int*   src     = (const int*)d_in[1];
    const int*   dst     = (const int*)d_in[2];
    const int*   batch   = (const int*)d_in[3];
    const float* W1      = (const float*)d_in[4];
    const float* b1      = (const float*)d_in[5];
    const float* W2      = (const float*)d_in[6];
    const float* b2      = (const float*)d_in[7];
    const float* gamma   = (const float*)d_in[8];
    const float* beta    = (const float*)d_in[9];
    const float* Wa_init = (const float*)d_in[10];
    const float* Wa_root = (const float*)d_in[11];
    const float* ba      = (const float*)d_in[12];
    const float* Wf1     = (const float*)d_in[13];
    const float* bf1     = (const float*)d_in[14];
    const float* Wf2     = (const float*)d_in[15];
    const float* bf2     = (const float*)d_in[16];
    const float* Wf3     = (const float*)d_in[17];
    const float* bf3     = (const float*)d_in[18];
    const float* Wf4     = (const float*)d_in[19];
    const float* bf4     = (const float*)d_in[20];
    float* out = (float*)d_out;

    // real device addresses of the scratch buffers (NOT the host shadows!)
    float* p_t0   = symaddr(g_t0);
    float* p_h1   = symaddr(g_h1);
    float* p_t1   = symaddr(g_t1);
    float* p_h2   = symaddr(g_h2);
    float* p_ur   = symaddr(g_ur);
    float* p_Wf   = symaddr(g_Wf);
    float* p_bf   = symaddr(g_bf);
    float* p_pool = symaddr(g_pool);
    float* p_m1   = symaddr(g_m1);
    float* p_m2   = symaddr(g_m2);
    float* p_m3   = symaddr(g_m3);

    const int GB_N = (NN + 255) / 256;       // 391
    const int GB_E = (EE + 255) / 256;       // 6250
    const int GB_P = (NN + 7) / 8;           // 12500 (warp per node, 8/block)
    const int GB_G = (NN + 63) / 64;         // 1563

    zero_kernel<<<GB_N, 256>>>();
    deg_kernel<<<GB_E, 256>>>(dst);
    scan1_kernel<<<SCAN_B, 256>>>();
    scan2_kernel<<<1, 512>>>();
    scan3_kernel<<<GB_N, 256>>>();
    csrfill_kernel<<<GB_E, 256>>>(src, dst);

    // SGConv 1: t0 = x @ W1 ; h1 = relu(prop_self(t0) + b1)
    gemm_nodes<K1, 64, D><<<GB_G, 256>>>(x, W1, nullptr, p_t0);
    prop_self_kernel<<<GB_P, 256>>>(p_t0, b1, p_h1);

    // SGConv 2: t1 = h1 @ W2 ; h2 = relu(prop_self(t1) + b2)
    gemm_nodes<D, 50, D><<<GB_G, 256>>>(p_h1, W2, nullptr, p_t1);
    prop_self_kernel<<<GB_P, 256>>>(p_t1, b2, p_h2);

    // BatchNorm stats + fold into ARMA weights
    bn_stats_kernel<<<GB_N, 128>>>();
    fold_kernel<<<1, 256>>>(gamma, beta, Wa_init, Wa_root, ba);

    // ARMA: ur = h2 @ Wf + bf  (u = cols 0..99, r = cols 100..199)
    gemm_nodes<D, 25, D2><<<GB_G, 256>>>(p_h2, p_Wf, p_bf, p_ur);

    // a = relu(prop_noself(u) + r), pooled by graph id (fused)
    arma_pool_kernel<<<GB_P, 256>>>(batch);

    // MLP head on [512, 100]
    mlp_gemm<100, 200, true><<<NG, 256>>>(p_pool, Wf1, bf1, p_m1);
    mlp_gemm<200, 300, true><<<NG, 256>>>(p_m1, Wf2, bf2, p_m2);
    mlp_gemm<300, 200, true><<<NG, 256>>>(p_m2, Wf3, bf3, p_m3);
    mlp_gemm<200, 1, false><<<NG, 32>>>(p_m3, Wf4, bf4, out);
}

// round 7
// speedup vs baseline: 1.1391x; 1.0149x over previous
#include <cuda_runtime.h>
#include <cuda_bf16.h>
#include <cstdint>

// ---------------- problem constants ----------------
#define NN 100000
#define EE 1600000
#define NG 512
#define D  100      // hidden dim
#define D2 200      // concat(u, r) width
#define K1 128      // input feature dim
#define SCAN_B ((NN + 255) / 256)   // 391 scan blocks

// ---------------- device scratch (static globals: allocation-free) ----------------
__device__ int   g_deg[NN];
__device__ int   g_cursor[NN];
__device__ int   g_off[NN];
__device__ int   g_part[512];
__device__ int   g_csr[EE];
__device__ float g_dinv_s[NN];
__device__ float g_dinv_n[NN];
__device__ float g_t0[(size_t)NN * D];
__device__ float g_h1[(size_t)NN * D];
__device__ float g_t1[(size_t)NN * D];
__device__ float g_h2[(size_t)NN * D];
__device__ float g_ur[(size_t)NN * D2];
__device__ float g_sum[D];
__device__ float g_sumsq[D];
__device__ float g_Wf[D * D2];
__device__ float g_bf[D2];
__device__ float g_pool[NG * D];
__device__ float g_m1[NG * 200];
__device__ float g_m2[NG * 300];
__device__ float g_m3[NG * 200];

// ---------------- graph-build kernels ----------------
__global__ void deg_kernel(const int* __restrict__ dst) {
    int e = blockIdx.x * blockDim.x + threadIdx.x;
    if (e < EE) atomicAdd(&g_deg[dst[e]], 1);
}

// block-level exclusive scan of g_deg into g_off (partial) + dinv computation
__global__ void scan1_kernel() {
    __shared__ int sh[256];
    int tid = threadIdx.x;
    int i = blockIdx.x * 256 + tid;
    int v = (i < NN) ? g_deg[i] : 0;
    sh[tid] = v;
    __syncthreads();
    for (int ofs = 1; ofs < 256; ofs <<= 1) {
        int t = (tid >= ofs) ? sh[tid - ofs] : 0;
        __syncthreads();
        sh[tid] += t;
        __syncthreads();
    }
    if (i < NN) {
        g_off[i] = sh[tid] - v;
        g_dinv_s[i] = rsqrtf((float)(v + 1));
        g_dinv_n[i] = (v > 0) ? rsqrtf((float)v) : 0.f;
    }
    if (tid == 255) g_part[blockIdx.x] = sh[255];
}

__global__ void scan2_kernel() {
    __shared__ int sh[512];
    int tid = threadIdx.x;
    int v = (tid < SCAN_B) ? g_part[tid] : 0;
    sh[tid] = v;
    __syncthreads();
    for (int ofs = 1; ofs < 512; ofs <<= 1) {
        int t = (tid >= ofs) ? sh[tid - ofs] : 0;
        __syncthreads();
        sh[tid] += t;
        __syncthreads();
    }
    g_part[tid] = sh[tid] - v;
}

// csrfill adds the scan partial inline (g_off stays block-partial everywhere)
__global__ void csrfill_kernel(const int* __restrict__ src, const int* __restrict__ dst) {
    int e = blockIdx.x * blockDim.x + threadIdx.x;
    if (e < EE) {
        int d = dst[e];
        int pos = g_off[d] + g_part[d >> 8] + atomicAdd(&g_cursor[d], 1);
        g_csr[pos] = src[e];
    }
}

// ---------------- node-level GEMM (R3 scalar version, best known) ----------------
// C[n x NC] = A[n x K] @ W[K x NC] (+bias); K-chunked, static shared <= 48KB.
// DOZERO: fuse the pipeline's zero-initialization into this (first) kernel.
template <int K, int KC, int NC, bool DOZERO>
__global__ void gemm_nodes(const float* __restrict__ A, const float* __restrict__ W,
                           const float* __restrict__ bias, float* __restrict__ C) {
    constexpr int ROWS = 64;
    constexpr int CT = (NC + 15) / 16;
    constexpr int CTP = CT * 16;
    __shared__ float Ws[KC * CTP];
    __shared__ float Xs[ROWS * (KC + 1)];
    int tid = threadIdx.x;
    int rowbase = blockIdx.x * ROWS;
    int tx = tid & 15, ty = tid >> 4;   // ty: 0..15 -> 4 rows each

    if (DOZERO) {
        int gidx = blockIdx.x * 256 + tid;
        int gstride = gridDim.x * 256;
        for (int k = gidx; k < NN; k += gstride) { g_deg[k] = 0; g_cursor[k] = 0; }
        for (int k = gidx; k < NG * D; k += gstride) g_pool[k] = 0.f;
        if (gidx < D) { g_sum[gidx] = 0.f; g_sumsq[gidx] = 0.f; }
    }

    float acc[4][CT];
#pragma unroll
    for (int i = 0; i < 4; i++)
#pragma unroll
        for (int j = 0; j < CT; j++) acc[i][j] = 0.f;

    for (int k0 = 0; k0 < K; k0 += KC) {
        for (int idx = tid; idx < KC * CTP; idx += 256) {
            int k = idx / CTP, c = idx % CTP;
            Ws[idx] = (c < NC) ? W[(k0 + k) * NC + c] : 0.f;
        }
        for (int idx = tid; idx < ROWS * KC; idx += 256) {
            int r = idx / KC, k = idx % KC;
            int gr = rowbase + r;
            Xs[r * (KC + 1) + k] = (gr < NN) ? A[(size_t)gr * K + k0 + k] : 0.f;
        }
        __syncthreads();

#pragma unroll 2
        for (int k = 0; k < KC; k++) {
            float a[4];
#pragma unroll
            for (int i = 0; i < 4; i++) a[i] = Xs[(ty * 4 + i) * (KC + 1) + k];
#pragma unroll
            for (int j = 0; j < CT; j++) {
                float w = Ws[k * CTP + tx + j * 16];
#pragma unroll
                for (int i = 0; i < 4; i++) acc[i][j] = fmaf(a[i], w, acc[i][j]);
            }
        }
        __syncthreads();
    }

#pragma unroll
    for (int i = 0; i < 4; i++) {
        int gr = rowbase + ty * 4 + i;
        if (gr >= NN) continue;
#pragma unroll
        for (int j = 0; j < CT; j++) {
            int c = tx + j * 16;
            if (c < NC) {
                float v = acc[i][j];
                if (bias) v += bias[c];
                C[(size_t)gr * NC + c] = v;
            }
        }
    }
}

// ---------------- GCN prop with self loops: warp/node, float4, uniform idx, unroll 4 ----------------
__global__ void prop_self_kernel(const float* __restrict__ T, const float* __restrict__ bias,
                                 float* __restrict__ out) {
    int node = blockIdx.x * 8 + (threadIdx.x >> 5);
    if (node >= NN) return;
    int lane = threadIdx.x & 31;
    int start = g_off[node] + g_part[node >> 8];
    int cnt = g_deg[node];
    float di = g_dinv_s[node];
    bool act = lane < 25;
    int col = lane * 4;
    float4 a = make_float4(0.f, 0.f, 0.f, 0.f);

    int e = 0;
    for (; e + 4 <= cnt; e += 4) {
        int j0 = g_csr[start + e];
        int j1 = g_csr[start + e + 1];
        int j2 = g_csr[start + e + 2];
        int j3 = g_csr[start + e + 3];
        float w0 = g_dinv_s[j0], w1 = g_dinv_s[j1];
        float w2 = g_dinv_s[j2], w3 = g_dinv_s[j3];
        if (act) {
            const float4 v0 = *(const float4*)(T + (size_t)j0 * D + col);
            const float4 v1 = *(const float4*)(T + (size_t)j1 * D + col);
            const float4 v2 = *(const float4*)(T + (size_t)j2 * D + col);
            const float4 v3 = *(const float4*)(T + (size_t)j3 * D + col);
            a.x = fmaf(w0, v0.x, a.x); a.y = fmaf(w0, v0.y, a.y);
            a.z = fmaf(w0, v0.z, a.z); a.w = fmaf(w0, v0.w, a.w);
            a.x = fmaf(w1, v1.x, a.x); a.y = fmaf(w1, v1.y, a.y);
            a.z = fmaf(w1, v1.z, a.z); a.w = fmaf(w1, v1.w, a.w);
            a.x = fmaf(w2, v2.x, a.x); a.y = fmaf(w2, v2.y, a.y);
            a.z = fmaf(w2, v2.z, a.z); a.w = fmaf(w2, v2.w, a.w);
            a.x = fmaf(w3, v3.x, a.x); a.y = fmaf(w3, v3.y, a.y);
            a.z = fmaf(w3, v3.z, a.z); a.w = fmaf(w3, v3.w, a.w);
        }
    }
    for (; e < cnt; e++) {
        int j = g_csr[start + e];
        float w = g_dinv_s[j];
        if (act) {
            const float4 v = *(const float4*)(T + (size_t)j * D + col);
            a.x = fmaf(w, v.x, a.x); a.y = fmaf(w, v.y, a.y);
            a.z = fmaf(w, v.z, a.z); a.w = fmaf(w, v.w, a.w);
        }
    }
    if (act) {
        const float4 v = *(const float4*)(T + (size_t)node * D + col);
        a.x = fmaf(di, v.x, a.x); a.y = fmaf(di, v.y, a.y);
        a.z = fmaf(di, v.z, a.z); a.w = fmaf(di, v.w, a.w);
        const float4 bb = *(const float4*)(bias + col);
        float4 o;
        o.x = fmaxf(fmaf(di, a.x, bb.x), 0.f);
        o.y = fmaxf(fmaf(di, a.y, bb.y), 0.f);
        o.z = fmaxf(fmaf(di, a.z, bb.z), 0.f);
        o.w = fmaxf(fmaf(di, a.w, bb.w), 0.f);
        *(float4*)(out + (size_t)node * D + col) = o;
    }
}

// ---------------- BatchNorm stats: register-column reduction, 1 atomic/block/col ----------------
__global__ void bn_stats_kernel() {
    int c = threadIdx.x;           // 128 threads, first 100 active
    if (c >= D) return;
    int r0 = blockIdx.x * 256;
    int r1 = min(r0 + 256, NN);
    float s = 0.f, q = 0.f;
    for (int r = r0; r < r1; r++) {
        float v = g_h2[(size_t)r * D + c];
        s += v;
        q = fmaf(v, v, q);
    }
    atomicAdd(&g_sum[c], s);
    atomicAdd(&g_sumsq[c], q);
}

// ---------------- fold BatchNorm affine into ARMA weights ----------------
// h = h2*s + t  =>  h@Wa = h2@(diag(s)Wa) + t@Wa
__global__ void fold_kernel(const float* __restrict__ gamma, const float* __restrict__ beta,
                            const float* __restrict__ Wa_init, const float* __restrict__ Wa_root,
                            const float* __restrict__ ba) {
    __shared__ float s[D], t[D];
    int tid = threadIdx.x;
    if (tid < D) {
        float mu = g_sum[tid] * (1.f / NN);
        float var = g_sumsq[tid] * (1.f / NN) - mu * mu;
        float rs = rsqrtf(var + 1e-5f);
        float sv = gamma[tid] * rs;
        s[tid] = sv;
        t[tid] = beta[tid] - mu * sv;
    }
    __syncthreads();
    for (int idx = tid; idx < D * D2; idx += blockDim.x) {
        int k = idx / D2, c = idx % D2;
        float w = (c < D) ? Wa_init[k * D + c] : Wa_root[k * D + (c - D)];
        g_Wf[idx] = s[k] * w;
    }
    for (int c = tid; c < D2; c += blockDim.x) {
        float acc;
        if (c < D) {
            acc = 0.f;
            for (int k = 0; k < D; k++) acc = fmaf(t[k], Wa_init[k * D + c], acc);
        } else {
            int cc = c - D;
            acc = ba[cc];
            for (int k = 0; k < D; k++) acc = fmaf(t[k], Wa_root[k * D + cc], acc);
        }
        g_bf[c] = acc;
    }
}

// ---------------- ARMA prop (no self loops) + root add + relu + pooled scatter ----------------
__global__ void arma_pool_kernel(const int* __restrict__ batch) {
    int node = blockIdx.x * 8 + (threadIdx.x >> 5);
    if (node >= NN) return;
    int lane = threadIdx.x & 31;
    int start = g_off[node] + g_part[node >> 8];
    int cnt = g_deg[node];
    float di = g_dinv_n[node];
    bool act = lane < 25;
    int col = lane * 4;
    float4 a = make_float4(0.f, 0.f, 0.f, 0.f);

    int e = 0;
    for (; e + 4 <= cnt; e += 4) {
        int j0 = g_csr[start + e];
        int j1 = g_csr[start + e + 1];
        int j2 = g_csr[start + e + 2];
        int j3 = g_csr[start + e + 3];
        float w0 = g_dinv_n[j0], w1 = g_dinv_n[j1];
        float w2 = g_dinv_n[j2], w3 = g_dinv_n[j3];
        if (act) {
            const float4 v0 = *(const float4*)(g_ur + (size_t)j0 * D2 + col);
            const float4 v1 = *(const float4*)(g_ur + (size_t)j1 * D2 + col);
            const float4 v2 = *(const float4*)(g_ur + (size_t)j2 * D2 + col);
            const float4 v3 = *(const float4*)(g_ur + (size_t)j3 * D2 + col);
            a.x = fmaf(w0, v0.x, a.x); a.y = fmaf(w0, v0.y, a.y);
            a.z = fmaf(w0, v0.z, a.z); a.w = fmaf(w0, v0.w, a.w);
            a.x = fmaf(w1, v1.x, a.x); a.y = fmaf(w1, v1.y, a.y);
            a.z = fmaf(w1, v1.z, a.z); a.w = fmaf(w1, v1.w, a.w);
            a.x = fmaf(w2, v2.x, a.x); a.y = fmaf(w2, v2.y, a.y);
            a.z = fmaf(w2, v2.z, a.z); a.w = fmaf(w2, v2.w, a.w);
            a.x = fmaf(w3, v3.x, a.x); a.y = fmaf(w3, v3.y, a.y);
            a.z = fmaf(w3, v3.z, a.z); a.w = fmaf(w3, v3.w, a.w);
        }
    }
    for (; e < cnt; e++) {
        int j = g_csr[start + e];
        float w = g_dinv_n[j];
        if (act) {
            const float4 v = *(const float4*)(g_ur + (size_t)j * D2 + col);
            a.x = fmaf(w, v.x, a.x); a.y = fmaf(w, v.y, a.y);
            a.z = fmaf(w, v.z, a.z); a.w = fmaf(w, v.w, a.w);
        }
    }
    if (act) {
        const float4 r = *(const float4*)(g_ur + (size_t)node * D2 + D + col);
        float v0 = fmaxf(fmaf(di, a.x, r.x), 0.f);
        float v1 = fmaxf(fmaf(di, a.y, r.y), 0.f);
        float v2 = fmaxf(fmaf(di, a.z, r.z), 0.f);
        float v3 = fmaxf(fmaf(di, a.w, r.w), 0.f);
        float* p = g_pool + (size_t)batch[node] * D + col;
        atomicAdd(&p[0], v0);
        atomicAdd(&p[1], v1);
        atomicAdd(&p[2], v2);
        atomicAdd(&p[3], v3);
    }
}

// ---------------- small MLP GEMM (row per block) ----------------
template <int K, int NC, bool RELU>
__global__ void mlp_gemm(const float* __restrict__ A, const float* __restrict__ W,
                         const float* __restrict__ b, float* __restrict__ C) {
    __shared__ float As[K];
    int r = blockIdx.x;
    for (int k = threadIdx.x; k < K; k += blockDim.x) As[k] = A[r * K + k];
    __syncthreads();
    for (int c = threadIdx.x; c < NC; c += blockDim.x) {
        float acc = b[c];
#pragma unroll 4
        for (int k = 0; k < K; k++) acc = fmaf(As[k], W[k * NC + c], acc);
        C[r * NC + c] = RELU ? fmaxf(acc, 0.f) : acc;
    }
}

// ---------------- host helper: real device address of a __device__ symbol ----------------
static float* symaddr(const void* sym) {
    void* p = nullptr;
    cudaGetSymbolAddress(&p, sym);
    return (float*)p;
}

// ---------------- launcher ----------------
extern "C" void kernel_launch(void* const* d_in, const int* in_sizes, int n_in,
                              void* d_out, int out_size) {
    const float* x       = (const float*)d_in[0];
    const int*   src     = (const int*)d_in[1];
    const int*   dst     = (const int*)d_in[2];
    const int*   batch   = (const int*)d_in[3];
    const float* W1      = (const float*)d_in[4];
    const float* b1      = (const float*)d_in[5];
    const float* W2      = (const float*)d_in[6];
    const float* b2      = (const float*)d_in[7];
    const float* gamma   = (const float*)d_in[8];
    const float* beta    = (const float*)d_in[9];
    const float* Wa_init = (const float*)d_in[10];
    const float* Wa_root = (const float*)d_in[11];
    const float* ba      = (const float*)d_in[12];
    const float* Wf1     = (const float*)d_in[13];
    const float* bf1     = (const float*)d_in[14];
    const float* Wf2     = (const float*)d_in[15];
    const float* bf2     = (const float*)d_in[16];
    const float* Wf3     = (const float*)d_in[17];
    const float* bf3     = (const float*)d_in[18];
    const float* Wf4     = (const float*)d_in[19];
    const float* bf4     = (const float*)d_in[20];
    float* out = (float*)d_out;

    // real device addresses of the scratch buffers (NOT the host shadows!)
    float* p_t0   = symaddr(g_t0);
    float* p_h1   = symaddr(g_h1);
    float* p_t1   = symaddr(g_t1);
    float* p_h2   = symaddr(g_h2);
    float* p_ur   = symaddr(g_ur);
    float* p_Wf   = symaddr(g_Wf);
    float* p_bf   = symaddr(g_bf);
    float* p_pool = symaddr(g_pool);
    float* p_m1   = symaddr(g_m1);
    float* p_m2   = symaddr(g_m2);
    float* p_m3   = symaddr(g_m3);

    const int GB_N = (NN + 255) / 256;       // 391
    const int GB_E = (EE + 255) / 256;       // 6250
    const int GB_P = (NN + 7) / 8;           // 12500 (warp per node, 8/block)
    const int GB_G = (NN + 63) / 64;         // 1563

    // 1: SGConv-1 GEMM (independent of graph build) + fused zero-init
    gemm_nodes<K1, 64, D, true><<<GB_G, 256>>>(x, W1, nullptr, p_t0);
    // 2-5: graph build
    deg_kernel<<<GB_E, 256>>>(dst);
    scan1_kernel<<<SCAN_B, 256>>>();
    scan2_kernel<<<1, 512>>>();
    csrfill_kernel<<<GB_E, 256>>>(src, dst);
    // 6: SGConv-1 propagation  (<- ncu profiles this launch)
    prop_self_kernel<<<GB_P, 256>>>(p_t0, b1, p_h1);

    // SGConv 2
    gemm_nodes<D, 50, D, false><<<GB_G, 256>>>(p_h1, W2, nullptr, p_t1);
    prop_self_kernel<<<GB_P, 256>>>(p_t1, b2, p_h2);

    // BatchNorm stats + fold into ARMA weights
    bn_stats_kernel<<<GB_N, 128>>>();
    fold_kernel<<<1, 256>>>(gamma, beta, Wa_init, Wa_root, ba);

    // ARMA: ur = h2 @ Wf + bf  (u = cols 0..99, r = cols 100..199)
    gemm_nodes<D, 25, D2, false><<<GB_G, 256>>>(p_h2, p_Wf, p_bf, p_ur);

    // a = relu(prop_noself(u) + r), pooled by graph id (fused)
    arma_pool_kernel<<<GB_P, 256>>>(batch);

    // MLP head on [512, 100]
    mlp_gemm<100, 200, true><<<NG, 256>>>(p_pool, Wf1, bf1, p_m1);
    mlp_gemm<200, 300, true><<<NG, 256>>>(p_m1, Wf2, bf2, p_m2);
    mlp_gemm<300, 200, true><<<NG, 256>>>(p_m2, Wf3, bf3, p_m3);
    mlp_gemm<200, 1, false><<<NG, 32>>>(p_m3, Wf4, bf4, out);
}

// round 8
// speedup vs baseline: 1.1880x; 1.0429x over previous
#include <cuda_runtime.h>
#include <cuda_bf16.h>
#include <cstdint>

// ---------------- problem constants ----------------
#define NN 100000
#define EE 1600000
#define NG 512
#define D  100      // hidden dim
#define D2 200      // concat(u, r) width
#define K1 128      // input feature dim
#define SCAN_B ((NN + 255) / 256)   // 391 scan blocks

// ---------------- device scratch (static globals: allocation-free) ----------------
__device__ int   g_deg[NN];
__device__ int   g_cursor[NN];
__device__ int   g_off[NN];
__device__ int   g_part[512];
__device__ int   g_csr[EE];
__device__ float g_dinv_s[NN];
__device__ float g_dinv_n[NN];
__device__ float g_t0[(size_t)NN * D];
__device__ float g_h1[(size_t)NN * D];
__device__ float g_t1[(size_t)NN * D];
__device__ float g_h2[(size_t)NN * D];
__device__ float g_u[(size_t)NN * D];     // ARMA propagated input (u = h@Wa_init')
__device__ float g_r[(size_t)NN * D];     // ARMA root part (r = h@Wa_root' + b')
__device__ float g_sum[D];
__device__ float g_sumsq[D];
__device__ float g_Wf[D * D2];
__device__ float g_bf[D2];
__device__ float g_pool[NG * D];
__device__ float g_m1[NG * 200];
__device__ float g_m2[NG * 300];
__device__ float g_m3[NG * 200];

// ---------------- init ----------------
__global__ void zero_kernel() {
    int i = blockIdx.x * blockDim.x + threadIdx.x;
    int stride = gridDim.x * blockDim.x;
    for (int k = i; k < NN; k += stride) { g_deg[k] = 0; g_cursor[k] = 0; }
    for (int k = i; k < NG * D; k += stride) g_pool[k] = 0.f;
    if (i < D) { g_sum[i] = 0.f; g_sumsq[i] = 0.f; }
}

// ---------------- graph-build kernels ----------------
__global__ void deg_kernel(const int* __restrict__ dst) {
    int e = blockIdx.x * blockDim.x + threadIdx.x;
    if (e < EE) atomicAdd(&g_deg[dst[e]], 1);
}

// block-level exclusive scan of g_deg into g_off (partial) + dinv computation
__global__ void scan1_kernel() {
    __shared__ int sh[256];
    int tid = threadIdx.x;
    int i = blockIdx.x * 256 + tid;
    int v = (i < NN) ? g_deg[i] : 0;
    sh[tid] = v;
    __syncthreads();
    for (int ofs = 1; ofs < 256; ofs <<= 1) {
        int t = (tid >= ofs) ? sh[tid - ofs] : 0;
        __syncthreads();
        sh[tid] += t;
        __syncthreads();
    }
    if (i < NN) {
        g_off[i] = sh[tid] - v;
        g_dinv_s[i] = rsqrtf((float)(v + 1));
        g_dinv_n[i] = (v > 0) ? rsqrtf((float)v) : 0.f;
    }
    if (tid == 255) g_part[blockIdx.x] = sh[255];
}

__global__ void scan2_kernel() {
    __shared__ int sh[512];
    int tid = threadIdx.x;
    int v = (tid < SCAN_B) ? g_part[tid] : 0;
    sh[tid] = v;
    __syncthreads();
    for (int ofs = 1; ofs < 512; ofs <<= 1) {
        int t = (tid >= ofs) ? sh[tid - ofs] : 0;
        __syncthreads();
        sh[tid] += t;
        __syncthreads();
    }
    g_part[tid] = sh[tid] - v;
}

// csrfill adds the scan partial inline (g_off stays block-partial everywhere)
__global__ void csrfill_kernel(const int* __restrict__ src, const int* __restrict__ dst) {
    int e = blockIdx.x * blockDim.x + threadIdx.x;
    if (e < EE) {
        int d = dst[e];
        int pos = g_off[d] + g_part[d >> 8] + atomicAdd(&g_cursor[d], 1);
        g_csr[pos] = src[e];
    }
}

// ---------------- node-level GEMM (scalar, best known) ----------------
// C[n x NC] = A[n x K] @ W[K x NC] (+bias); K-chunked, static shared <= 48KB.
// SPLIT: write cols [0,100) to C and cols [100,200) to C2 (both [n x D]).
template <int K, int KC, int NC, bool SPLIT>
__global__ void gemm_nodes(const float* __restrict__ A, const float* __restrict__ W,
                           const float* __restrict__ bias, float* __restrict__ C,
                           float* __restrict__ C2) {
    constexpr int ROWS = 64;
    constexpr int CT = (NC + 15) / 16;
    constexpr int CTP = CT * 16;
    __shared__ float Ws[KC * CTP];
    __shared__ float Xs[ROWS * (KC + 1)];
    int tid = threadIdx.x;
    int rowbase = blockIdx.x * ROWS;
    int tx = tid & 15, ty = tid >> 4;   // ty: 0..15 -> 4 rows each

    float acc[4][CT];
#pragma unroll
    for (int i = 0; i < 4; i++)
#pragma unroll
        for (int j = 0; j < CT; j++) acc[i][j] = 0.f;

    for (int k0 = 0; k0 < K; k0 += KC) {
        for (int idx = tid; idx < KC * CTP; idx += 256) {
            int k = idx / CTP, c = idx % CTP;
            Ws[idx] = (c < NC) ? W[(k0 + k) * NC + c] : 0.f;
        }
        for (int idx = tid; idx < ROWS * KC; idx += 256) {
            int r = idx / KC, k = idx % KC;
            int gr = rowbase + r;
            Xs[r * (KC + 1) + k] = (gr < NN) ? A[(size_t)gr * K + k0 + k] : 0.f;
        }
        __syncthreads();

#pragma unroll 2
        for (int k = 0; k < KC; k++) {
            float a[4];
#pragma unroll
            for (int i = 0; i < 4; i++) a[i] = Xs[(ty * 4 + i) * (KC + 1) + k];
#pragma unroll
            for (int j = 0; j < CT; j++) {
                float w = Ws[k * CTP + tx + j * 16];
#pragma unroll
                for (int i = 0; i < 4; i++) acc[i][j] = fmaf(a[i], w, acc[i][j]);
            }
        }
        __syncthreads();
    }

#pragma unroll
    for (int i = 0; i < 4; i++) {
        int gr = rowbase + ty * 4 + i;
        if (gr >= NN) continue;
#pragma unroll
        for (int j = 0; j < CT; j++) {
            int c = tx + j * 16;
            if (c < NC) {
                float v = acc[i][j];
                if (bias) v += bias[c];
                if (SPLIT) {
                    if (c < D) C[(size_t)gr * D + c] = v;
                    else       C2[(size_t)gr * D + (c - D)] = v;
                } else {
                    C[(size_t)gr * NC + c] = v;
                }
            }
        }
    }
}

// ---------------- GCN prop with self loops: warp/node, float4, uniform idx, unroll 4 ----------------
__global__ void prop_self_kernel(const float* __restrict__ T, const float* __restrict__ bias,
                                 float* __restrict__ out) {
    int node = blockIdx.x * 8 + (threadIdx.x >> 5);
    if (node >= NN) return;
    int lane = threadIdx.x & 31;
    int start = g_off[node] + g_part[node >> 8];
    int cnt = g_deg[node];
    float di = g_dinv_s[node];
    bool act = lane < 25;
    int col = lane * 4;
    float4 a = make_float4(0.f, 0.f, 0.f, 0.f);

    int e = 0;
    for (; e + 4 <= cnt; e += 4) {
        int j0 = g_csr[start + e];
        int j1 = g_csr[start + e + 1];
        int j2 = g_csr[start + e + 2];
        int j3 = g_csr[start + e + 3];
        float w0 = g_dinv_s[j0], w1 = g_dinv_s[j1];
        float w2 = g_dinv_s[j2], w3 = g_dinv_s[j3];
        if (act) {
            const float4 v0 = *(const float4*)(T + (size_t)j0 * D + col);
            const float4 v1 = *(const float4*)(T + (size_t)j1 * D + col);
            const float4 v2 = *(const float4*)(T + (size_t)j2 * D + col);
            const float4 v3 = *(const float4*)(T + (size_t)j3 * D + col);
            a.x = fmaf(w0, v0.x, a.x); a.y = fmaf(w0, v0.y, a.y);
            a.z = fmaf(w0, v0.z, a.z); a.w = fmaf(w0, v0.w, a.w);
            a.x = fmaf(w1, v1.x, a.x); a.y = fmaf(w1, v1.y, a.y);
            a.z = fmaf(w1, v1.z, a.z); a.w = fmaf(w1, v1.w, a.w);
            a.x = fmaf(w2, v2.x, a.x); a.y = fmaf(w2, v2.y, a.y);
            a.z = fmaf(w2, v2.z, a.z); a.w = fmaf(w2, v2.w, a.w);
            a.x = fmaf(w3, v3.x, a.x); a.y = fmaf(w3, v3.y, a.y);
            a.z = fmaf(w3, v3.z, a.z); a.w = fmaf(w3, v3.w, a.w);
        }
    }
    for (; e < cnt; e++) {
        int j = g_csr[start + e];
        float w = g_dinv_s[j];
        if (act) {
            const float4 v = *(const float4*)(T + (size_t)j * D + col);
            a.x = fmaf(w, v.x, a.x); a.y = fmaf(w, v.y, a.y);
            a.z = fmaf(w, v.z, a.z); a.w = fmaf(w, v.w, a.w);
        }
    }
    if (act) {
        const float4 v = *(const float4*)(T + (size_t)node * D + col);
        a.x = fmaf(di, v.x, a.x); a.y = fmaf(di, v.y, a.y);
        a.z = fmaf(di, v.z, a.z); a.w = fmaf(di, v.w, a.w);
        const float4 bb = *(const float4*)(bias + col);
        float4 o;
        o.x = fmaxf(fmaf(di, a.x, bb.x), 0.f);
        o.y = fmaxf(fmaf(di, a.y, bb.y), 0.f);
        o.z = fmaxf(fmaf(di, a.z, bb.z), 0.f);
        o.w = fmaxf(fmaf(di, a.w, bb.w), 0.f);
        *(float4*)(out + (size_t)node * D + col) = o;
    }
}

// ---------------- BatchNorm stats: register-column reduction, 1 atomic/block/col ----------------
__global__ void bn_stats_kernel() {
    int c = threadIdx.x;           // 128 threads, first 100 active
    if (c >= D) return;
    int r0 = blockIdx.x * 256;
    int r1 = min(r0 + 256, NN);
    float s = 0.f, q = 0.f;
    for (int r = r0; r < r1; r++) {
        float v = g_h2[(size_t)r * D + c];
        s += v;
        q = fmaf(v, v, q);
    }
    atomicAdd(&g_sum[c], s);
    atomicAdd(&g_sumsq[c], q);
}

// ---------------- fold BatchNorm affine into ARMA weights ----------------
// h = h2*s + t  =>  h@Wa = h2@(diag(s)Wa) + t@Wa
__global__ void fold_kernel(const float* __restrict__ gamma, const float* __restrict__ beta,
                            const float* __restrict__ Wa_init, const float* __restrict__ Wa_root,
                            const float* __restrict__ ba) {
    __shared__ float s[D], t[D];
    int tid = threadIdx.x;
    if (tid < D) {
        float mu = g_sum[tid] * (1.f / NN);
        float var = g_sumsq[tid] * (1.f / NN) - mu * mu;
        float rs = rsqrtf(var + 1e-5f);
        float sv = gamma[tid] * rs;
        s[tid] = sv;
        t[tid] = beta[tid] - mu * sv;
    }
    __syncthreads();
    for (int idx = tid; idx < D * D2; idx += blockDim.x) {
        int k = idx / D2, c = idx % D2;
        float w = (c < D) ? Wa_init[k * D + c] : Wa_root[k * D + (c - D)];
        g_Wf[idx] = s[k] * w;
    }
    for (int c = tid; c < D2; c += blockDim.x) {
        float acc;
        if (c < D) {
            acc = 0.f;
            for (int k = 0; k < D; k++) acc = fmaf(t[k], Wa_init[k * D + c], acc);
        } else {
            int cc = c - D;
            acc = ba[cc];
            for (int k = 0; k < D; k++) acc = fmaf(t[k], Wa_root[k * D + cc], acc);
        }
        g_bf[c] = acc;
    }
}

// ---------------- ARMA prop (no self loops) + root + relu + block-pooled scatter ----------------
// batch is sorted and NN = 8 * gridDim.x exactly; a block's 8 nodes share one
// graph iff batch[first] == batch[last] -> accumulate in smem, 1 atomic set/block.
__global__ void arma_pool_kernel(const int* __restrict__ batch) {
    __shared__ float sacc[D];
    __shared__ int s_b0, s_same;
    int wid = threadIdx.x >> 5;
    int lane = threadIdx.x & 31;
    int node = blockIdx.x * 8 + wid;

    if (threadIdx.x == 0) {
        int b0 = batch[blockIdx.x * 8];
        int b7 = batch[blockIdx.x * 8 + 7];
        s_b0 = b0;
        s_same = (b0 == b7) ? 1 : 0;
    }
    if (threadIdx.x < D) sacc[threadIdx.x] = 0.f;

    int start = g_off[node] + g_part[node >> 8];
    int cnt = g_deg[node];
    float di = g_dinv_n[node];
    bool act = lane < 25;
    int col = lane * 4;
    float4 a = make_float4(0.f, 0.f, 0.f, 0.f);

    int e = 0;
    for (; e + 4 <= cnt; e += 4) {
        int j0 = g_csr[start + e];
        int j1 = g_csr[start + e + 1];
        int j2 = g_csr[start + e + 2];
        int j3 = g_csr[start + e + 3];
        float w0 = g_dinv_n[j0], w1 = g_dinv_n[j1];
        float w2 = g_dinv_n[j2], w3 = g_dinv_n[j3];
        if (act) {
            const float4 v0 = *(const float4*)(g_u + (size_t)j0 * D + col);
            const float4 v1 = *(const float4*)(g_u + (size_t)j1 * D + col);
            const float4 v2 = *(const float4*)(g_u + (size_t)j2 * D + col);
            const float4 v3 = *(const float4*)(g_u + (size_t)j3 * D + col);
            a.x = fmaf(w0, v0.x, a.x); a.y = fmaf(w0, v0.y, a.y);
            a.z = fmaf(w0, v0.z, a.z); a.w = fmaf(w0, v0.w, a.w);
            a.x = fmaf(w1, v1.x, a.x); a.y = fmaf(w1, v1.y, a.y);
            a.z = fmaf(w1, v1.z, a.z); a.w = fmaf(w1, v1.w, a.w);
            a.x = fmaf(w2, v2.x, a.x); a.y = fmaf(w2, v2.y, a.y);
            a.z = fmaf(w2, v2.z, a.z); a.w = fmaf(w2, v2.w, a.w);
            a.x = fmaf(w3, v3.x, a.x); a.y = fmaf(w3, v3.y, a.y);
            a.z = fmaf(w3, v3.z, a.z); a.w = fmaf(w3, v3.w, a.w);
        }
    }
    for (; e < cnt; e++) {
        int j = g_csr[start + e];
        float w = g_dinv_n[j];
        if (act) {
            const float4 v = *(const float4*)(g_u + (size_t)j * D + col);
            a.x = fmaf(w, v.x, a.x); a.y = fmaf(w, v.y, a.y);
            a.z = fmaf(w, v.z, a.z); a.w = fmaf(w, v.w, a.w);
        }
    }

    float v0 = 0.f, v1 = 0.f, v2 = 0.f, v3 = 0.f;
    if (act) {
        const float4 r = *(const float4*)(g_r + (size_t)node * D + col);
        v0 = fmaxf(fmaf(di, a.x, r.x), 0.f);
        v1 = fmaxf(fmaf(di, a.y, r.y), 0.f);
        v2 = fmaxf(fmaf(di, a.z, r.z), 0.f);
        v3 = fmaxf(fmaf(di, a.w, r.w), 0.f);
    }
    __syncthreads();                     // sacc zeroed + s_same/s_b0 visible
    if (s_same) {
        if (act) {
            atomicAdd(&sacc[col],     v0);
            atomicAdd(&sacc[col + 1], v1);
            atomicAdd(&sacc[col + 2], v2);
            atomicAdd(&sacc[col + 3], v3);
        }
        __syncthreads();
        if (threadIdx.x < D)
            atomicAdd(&g_pool[(size_t)s_b0 * D + threadIdx.x], sacc[threadIdx.x]);
    } else {
        if (act) {
            float* p = g_pool + (size_t)batch[node] * D + col;
            atomicAdd(&p[0], v0);
            atomicAdd(&p[1], v1);
            atomicAdd(&p[2], v2);
            atomicAdd(&p[3], v3);
        }
    }
}

// ---------------- small MLP GEMM (row per block) ----------------
template <int K, int NC, bool RELU>
__global__ void mlp_gemm(const float* __restrict__ A, const float* __restrict__ W,
                         const float* __restrict__ b, float* __restrict__ C) {
    __shared__ float As[K];
    int r = blockIdx.x;
    for (int k = threadIdx.x; k < K; k += blockDim.x) As[k] = A[r * K + k];
    __syncthreads();
    for (int c = threadIdx.x; c < NC; c += blockDim.x) {
        float acc = b[c];
#pragma unroll 4
        for (int k = 0; k < K; k++) acc = fmaf(As[k], W[k * NC + c], acc);
        C[r * NC + c] = RELU ? fmaxf(acc, 0.f) : acc;
    }
}

// ---------------- host helper: real device address of a __device__ symbol ----------------
static float* symaddr(const void* sym) {
    void* p = nullptr;
    cudaGetSymbolAddress(&p, sym);
    return (float*)p;
}

// ---------------- launcher ----------------
extern "C" void kernel_launch(void* const* d_in, const int* in_sizes, int n_in,
                              void* d_out, int out_size) {
    const float* x       = (const float*)d_in[0];
    const int*   src     = (const int*)d_in[1];
    const int*   dst     = (const int*)d_in[2];
    const int*   batch   = (const int*)d_in[3];
    const float* W1      = (const float*)d_in[4];
    const float* b1      = (const float*)d_in[5];
    const float* W2      = (const float*)d_in[6];
    const float* b2      = (const float*)d_in[7];
    const float* gamma   = (const float*)d_in[8];
    const float* beta    = (const float*)d_in[9];
    const float* Wa_init = (const float*)d_in[10];
    const float* Wa_root = (const float*)d_in[11];
    const float* ba      = (const float*)d_in[12];
    const float* Wf1     = (const float*)d_in[13];
    const float* bf1     = (const float*)d_in[14];
    const float* Wf2     = (const float*)d_in[15];
    const float* bf2     = (const float*)d_in[16];
    const float* Wf3     = (const float*)d_in[17];
    const float* bf3     = (const float*)d_in[18];
    const float* Wf4     = (const float*)d_in[19];
    const float* bf4     = (const float*)d_in[20];
    float* out = (float*)d_out;

    // real device addresses of the scratch buffers (NOT the host shadows!)
    float* p_t0   = symaddr(g_t0);
    float* p_h1   = symaddr(g_h1);
    float* p_t1   = symaddr(g_t1);
    float* p_h2   = symaddr(g_h2);
    float* p_u    = symaddr(g_u);
    float* p_r    = symaddr(g_r);
    float* p_Wf   = symaddr(g_Wf);
    float* p_bf   = symaddr(g_bf);
    float* p_pool = symaddr(g_pool);
    float* p_m1   = symaddr(g_m1);
    float* p_m2   = symaddr(g_m2);
    float* p_m3   = symaddr(g_m3);

    const int GB_N = (NN + 255) / 256;       // 391
    const int GB_E = (EE + 255) / 256;       // 6250
    const int GB_P = (NN + 7) / 8;           // 12500 (warp per node, 8/block)
    const int GB_G = (NN + 63) / 64;         // 1563

    // 1-3: init + graph build (first half)
    zero_kernel<<<GB_N, 256>>>();
    deg_kernel<<<GB_E, 256>>>(dst);
    scan1_kernel<<<SCAN_B, 256>>>();
    // 4: SGConv-1 GEMM (independent)  <- ncu profiles launch #4
    gemm_nodes<K1, 64, D, false><<<GB_G, 256>>>(x, W1, nullptr, p_t0, nullptr);
    // 5-6: graph build (second half)
    scan2_kernel<<<1, 512>>>();
    csrfill_kernel<<<GB_E, 256>>>(src, dst);

    // SGConv 1 propagation
    prop_self_kernel<<<GB_P, 256>>>(p_t0, b1, p_h1);

    // SGConv 2
    gemm_nodes<D, 50, D, false><<<GB_G, 256>>>(p_h1, W2, nullptr, p_t1, nullptr);
    prop_self_kernel<<<GB_P, 256>>>(p_t1, b2, p_h2);

    // BatchNorm stats + fold into ARMA weights
    bn_stats_kernel<<<GB_N, 128>>>();
    fold_kernel<<<1, 256>>>(gamma, beta, Wa_init, Wa_root, ba);

    // ARMA: [u | r] = h2 @ Wf + bf, written split
    gemm_nodes<D, 25, D2, true><<<GB_G, 256>>>(p_h2, p_Wf, p_bf, p_u, p_r);

    // a = relu(prop_noself(u) + r), pooled by graph id (fused, block-pooled)
    arma_pool_kernel<<<GB_P, 256>>>(batch);

    // MLP head on [512, 100]
    mlp_gemm<100, 200, true><<<NG, 256>>>(p_pool, Wf1, bf1, p_m1);
    mlp_gemm<200, 300, true><<<NG, 256>>>(p_m1, Wf2, bf2, p_m2);
    mlp_gemm<300, 200, true><<<NG, 256>>>(p_m2, Wf3, bf3, p_m3);
    mlp_gemm<200, 1, false><<<NG, 32>>>(p_m3, Wf4, bf4, out);
}

// round 9
// speedup vs baseline: 1.2989x; 1.0933x over previous
#include <cuda_runtime.h>
#include <cuda_bf16.h>
#include <cstdint>

// ---------------- problem constants ----------------
#define NN 100000
#define EE 1600000
#define NG 512
#define D  100      // hidden dim
#define K1 128      // input feature dim
#define SCAN_B ((NN + 255) / 256)   // 391 scan blocks

// ---------------- device scratch (static globals: allocation-free) ----------------
__device__ int   g_deg[NN];
__device__ int   g_cursor[NN];
__device__ int   g_off[NN];
__device__ int   g_part[512];
__device__ int   g_csr[EE];
__device__ float g_dinv_s[NN];
__device__ float g_dinv_n[NN];
__device__ float g_t0[(size_t)NN * D];
__device__ float g_h1[(size_t)NN * D];
__device__ float g_t1[(size_t)NN * D];
__device__ float g_h2[(size_t)NN * D];
__device__ float g_u[(size_t)NN * D];     // ARMA propagated input
__device__ float g_r[(size_t)NN * D];     // ARMA root part
__device__ float g_sum[D];
__device__ float g_sumsq[D];
__device__ float g_Wu[D * D];
__device__ float g_bu[D];
__device__ float g_Wr[D * D];
__device__ float g_br[D];
__device__ float g_pool[NG * D];
__device__ float g_m1[NG * 200];
__device__ float g_m2[NG * 300];
__device__ float g_m3[NG * 200];

// ---------------- init ----------------
__global__ void zero_kernel() {
    int i = blockIdx.x * blockDim.x + threadIdx.x;
    int stride = gridDim.x * blockDim.x;
    for (int k = i; k < NN; k += stride) { g_deg[k] = 0; g_cursor[k] = 0; }
    for (int k = i; k < NG * D; k += stride) g_pool[k] = 0.f;
    if (i < D) { g_sum[i] = 0.f; g_sumsq[i] = 0.f; }
}

// ---------------- graph-build kernels ----------------
__global__ void deg_kernel(const int* __restrict__ dst) {
    int e = blockIdx.x * blockDim.x + threadIdx.x;
    if (e < EE) atomicAdd(&g_deg[dst[e]], 1);
}

__global__ void scan1_kernel() {
    __shared__ int sh[256];
    int tid = threadIdx.x;
    int i = blockIdx.x * 256 + tid;
    int v = (i < NN) ? g_deg[i] : 0;
    sh[tid] = v;
    __syncthreads();
    for (int ofs = 1; ofs < 256; ofs <<= 1) {
        int t = (tid >= ofs) ? sh[tid - ofs] : 0;
        __syncthreads();
        sh[tid] += t;
        __syncthreads();
    }
    if (i < NN) {
        g_off[i] = sh[tid] - v;
        g_dinv_s[i] = rsqrtf((float)(v + 1));
        g_dinv_n[i] = (v > 0) ? rsqrtf((float)v) : 0.f;
    }
    if (tid == 255) g_part[blockIdx.x] = sh[255];
}

__global__ void scan2_kernel() {
    __shared__ int sh[512];
    int tid = threadIdx.x;
    int v = (tid < SCAN_B) ? g_part[tid] : 0;
    sh[tid] = v;
    __syncthreads();
    for (int ofs = 1; ofs < 512; ofs <<= 1) {
        int t = (tid >= ofs) ? sh[tid - ofs] : 0;
        __syncthreads();
        sh[tid] += t;
        __syncthreads();
    }
    g_part[tid] = sh[tid] - v;
}

__global__ void csrfill_kernel(const int* __restrict__ src, const int* __restrict__ dst) {
    int e = blockIdx.x * blockDim.x + threadIdx.x;
    if (e < EE) {
        int d = dst[e];
        int pos = g_off[d] + g_part[d >> 8] + atomicAdd(&g_cursor[d], 1);
        g_csr[pos] = src[e];
    }
}

// ---------------- register-tiled node GEMM:  C[n x 100] = A[n x K] @ W[K x 100] (+bias) ----------
// Block: 80 rows x 100 cols, 256 threads (250 active: 25 col-groups x 10 row-groups).
// Thread: 8 rows x 4 cols. Per k: 2 LDS.128 (x, broadcast) + 1 LDS.128 (w) + 32 FMA.
template <int K, int KC>
__global__ void gemm_rf(const float* __restrict__ A, const float* __restrict__ W,
                        const float* __restrict__ bias, float* __restrict__ C) {
    constexpr int ROWS = 80;
    constexpr int XP = 84;               // pad: 4-way-max STS conflicts, float4-aligned
    __shared__ __align__(16) float Xs[KC * XP];
    __shared__ __align__(16) float Ws[KC * D];
    int tid = threadIdx.x;
    int rowbase = blockIdx.x * ROWS;
    bool active = tid < 250;
    int cx = tid % 25;                   // col group: cols 4*cx .. 4*cx+3
    int ry = active ? (tid / 25) : 0;    // row group: rows 8*ry .. 8*ry+7

    float4 acc[8];
#pragma unroll
    for (int i = 0; i < 8; i++) acc[i] = make_float4(0.f, 0.f, 0.f, 0.f);

    for (int k0 = 0; k0 < K; k0 += KC) {
        for (int idx = tid; idx < KC * D; idx += 256) {
            Ws[idx] = W[(k0 + idx / D) * D + (idx % D)];
        }
        for (int idx = tid; idx < ROWS * KC; idx += 256) {
            int r = idx / KC, k = idx % KC;
            int gr = rowbase + r;
            Xs[k * XP + r] = (gr < NN) ? A[(size_t)gr * K + k0 + k] : 0.f;
        }
        __syncthreads();

#pragma unroll 2
        for (int k = 0; k < KC; k++) {
            const float4 w  = *(const float4*)&Ws[k * D + cx * 4];
            const float4 xa = *(const float4*)&Xs[k * XP + ry * 8];
            const float4 xb = *(const float4*)&Xs[k * XP + ry * 8 + 4];
            float x[8] = {xa.x, xa.y, xa.z, xa.w, xb.x, xb.y, xb.z, xb.w};
#pragma unroll
            for (int i = 0; i < 8; i++) {
                acc[i].x = fmaf(x[i], w.x, acc[i].x);
                acc[i].y = fmaf(x[i], w.y, acc[i].y);
                acc[i].z = fmaf(x[i], w.z, acc[i].z);
                acc[i].w = fmaf(x[i], w.w, acc[i].w);
            }
        }
        __syncthreads();
    }

    if (active) {
        float4 bb = make_float4(0.f, 0.f, 0.f, 0.f);
        if (bias) bb = *(const float4*)&bias[cx * 4];
#pragma unroll
        for (int i = 0; i < 8; i++) {
            int gr = rowbase + ry * 8 + i;
            if (gr < NN) {
                float4 o;
                o.x = acc[i].x + bb.x; o.y = acc[i].y + bb.y;
                o.z = acc[i].z + bb.z; o.w = acc[i].w + bb.w;
                *(float4*)&C[(size_t)gr * D + cx * 4] = o;
            }
        }
    }
}

// ---------------- GCN prop with self loops: warp/node, float4, uniform idx, unroll 4 ----------------
__global__ void prop_self_kernel(const float* __restrict__ T, const float* __restrict__ bias,
                                 float* __restrict__ out) {
    int node = blockIdx.x * 8 + (threadIdx.x >> 5);
    if (node >= NN) return;
    int lane = threadIdx.x & 31;
    int start = g_off[node] + g_part[node >> 8];
    int cnt = g_deg[node];
    float di = g_dinv_s[node];
    bool act = lane < 25;
    int col = lane * 4;
    float4 a = make_float4(0.f, 0.f, 0.f, 0.f);

    int e = 0;
    for (; e + 4 <= cnt; e += 4) {
        int j0 = g_csr[start + e];
        int j1 = g_csr[start + e + 1];
        int j2 = g_csr[start + e + 2];
        int j3 = g_csr[start + e + 3];
        float w0 = g_dinv_s[j0], w1 = g_dinv_s[j1];
        float w2 = g_dinv_s[j2], w3 = g_dinv_s[j3];
        if (act) {
            const float4 v0 = *(const float4*)(T + (size_t)j0 * D + col);
            const float4 v1 = *(const float4*)(T + (size_t)j1 * D + col);
            const float4 v2 = *(const float4*)(T + (size_t)j2 * D + col);
            const float4 v3 = *(const float4*)(T + (size_t)j3 * D + col);
            a.x = fmaf(w0, v0.x, a.x); a.y = fmaf(w0, v0.y, a.y);
            a.z = fmaf(w0, v0.z, a.z); a.w = fmaf(w0, v0.w, a.w);
            a.x = fmaf(w1, v1.x, a.x); a.y = fmaf(w1, v1.y, a.y);
            a.z = fmaf(w1, v1.z, a.z); a.w = fmaf(w1, v1.w, a.w);
            a.x = fmaf(w2, v2.x, a.x); a.y = fmaf(w2, v2.y, a.y);
            a.z = fmaf(w2, v2.z, a.z); a.w = fmaf(w2, v2.w, a.w);
            a.x = fmaf(w3, v3.x, a.x); a.y = fmaf(w3, v3.y, a.y);
            a.z = fmaf(w3, v3.z, a.z); a.w = fmaf(w3, v3.w, a.w);
        }
    }
    for (; e < cnt; e++) {
        int j = g_csr[start + e];
        float w = g_dinv_s[j];
        if (act) {
            const float4 v = *(const float4*)(T + (size_t)j * D + col);
            a.x = fmaf(w, v.x, a.x); a.y = fmaf(w, v.y, a.y);
            a.z = fmaf(w, v.z, a.z); a.w = fmaf(w, v.w, a.w);
        }
    }
    if (act) {
        const float4 v = *(const float4*)(T + (size_t)node * D + col);
        a.x = fmaf(di, v.x, a.x); a.y = fmaf(di, v.y, a.y);
        a.z = fmaf(di, v.z, a.z); a.w = fmaf(di, v.w, a.w);
        const float4 bb = *(const float4*)(bias + col);
        float4 o;
        o.x = fmaxf(fmaf(di, a.x, bb.x), 0.f);
        o.y = fmaxf(fmaf(di, a.y, bb.y), 0.f);
        o.z = fmaxf(fmaf(di, a.z, bb.z), 0.f);
        o.w = fmaxf(fmaf(di, a.w, bb.w), 0.f);
        *(float4*)(out + (size_t)node * D + col) = o;
    }
}

// ---------------- BatchNorm stats: register-column reduction, 1 atomic/block/col ----------------
__global__ void bn_stats_kernel() {
    int c = threadIdx.x;
    if (c >= D) return;
    int r0 = blockIdx.x * 256;
    int r1 = min(r0 + 256, NN);
    float s = 0.f, q = 0.f;
    for (int r = r0; r < r1; r++) {
        float v = g_h2[(size_t)r * D + c];
        s += v;
        q = fmaf(v, v, q);
    }
    atomicAdd(&g_sum[c], s);
    atomicAdd(&g_sumsq[c], q);
}

// ---------------- fold BatchNorm affine into ARMA weights (split u/r) ----------------
// h = h2*s + t  =>  h@Wa = h2@(diag(s)Wa) + t@Wa
__global__ void fold_kernel(const float* __restrict__ gamma, const float* __restrict__ beta,
                            const float* __restrict__ Wa_init, const float* __restrict__ Wa_root,
                            const float* __restrict__ ba) {
    __shared__ float s[D], t[D];
    int tid = threadIdx.x;
    if (tid < D) {
        float mu = g_sum[tid] * (1.f / NN);
        float var = g_sumsq[tid] * (1.f / NN) - mu * mu;
        float rs = rsqrtf(var + 1e-5f);
        float sv = gamma[tid] * rs;
        s[tid] = sv;
        t[tid] = beta[tid] - mu * sv;
    }
    __syncthreads();
    for (int idx = tid; idx < D * D; idx += blockDim.x) {
        int k = idx / D;
        g_Wu[idx] = s[k] * Wa_init[idx];
        g_Wr[idx] = s[k] * Wa_root[idx];
    }
    for (int c = tid; c < D; c += blockDim.x) {
        float au = 0.f, ar = ba[c];
        for (int k = 0; k < D; k++) {
            au = fmaf(t[k], Wa_init[k * D + c], au);
            ar = fmaf(t[k], Wa_root[k * D + c], ar);
        }
        g_bu[c] = au;
        g_br[c] = ar;
    }
}

// ---------------- ARMA prop (no self loops) + root + relu + block-pooled scatter ----------------
__global__ void arma_pool_kernel(const int* __restrict__ batch) {
    __shared__ float sacc[D];
    __shared__ int s_b0, s_same;
    int wid = threadIdx.x >> 5;
    int lane = threadIdx.x & 31;
    int node = blockIdx.x * 8 + wid;

    if (threadIdx.x == 0) {
        int b0 = batch[blockIdx.x * 8];
        int b7 = batch[blockIdx.x * 8 + 7];
        s_b0 = b0;
        s_same = (b0 == b7) ? 1 : 0;
    }
    if (threadIdx.x < D) sacc[threadIdx.x] = 0.f;

    int start = g_off[node] + g_part[node >> 8];
    int cnt = g_deg[node];
    float di = g_dinv_n[node];
    bool act = lane < 25;
    int col = lane * 4;
    float4 a = make_float4(0.f, 0.f, 0.f, 0.f);

    int e = 0;
    for (; e + 4 <= cnt; e += 4) {
        int j0 = g_csr[start + e];
        int j1 = g_csr[start + e + 1];
        int j2 = g_csr[start + e + 2];
        int j3 = g_csr[start + e + 3];
        float w0 = g_dinv_n[j0], w1 = g_dinv_n[j1];
        float w2 = g_dinv_n[j2], w3 = g_dinv_n[j3];
        if (act) {
            const float4 v0 = *(const float4*)(g_u + (size_t)j0 * D + col);
            const float4 v1 = *(const float4*)(g_u + (size_t)j1 * D + col);
            const float4 v2 = *(const float4*)(g_u + (size_t)j2 * D + col);
            const float4 v3 = *(const float4*)(g_u + (size_t)j3 * D + col);
            a.x = fmaf(w0, v0.x, a.x); a.y = fmaf(w0, v0.y, a.y);
            a.z = fmaf(w0, v0.z, a.z); a.w = fmaf(w0, v0.w, a.w);
            a.x = fmaf(w1, v1.x, a.x); a.y = fmaf(w1, v1.y, a.y);
            a.z = fmaf(w1, v1.z, a.z); a.w = fmaf(w1, v1.w, a.w);
            a.x = fmaf(w2, v2.x, a.x); a.y = fmaf(w2, v2.y, a.y);
            a.z = fmaf(w2, v2.z, a.z); a.w = fmaf(w2, v2.w, a.w);
            a.x = fmaf(w3, v3.x, a.x); a.y = fmaf(w3, v3.y, a.y);
            a.z = fmaf(w3, v3.z, a.z); a.w = fmaf(w3, v3.w, a.w);
        }
    }
    for (; e < cnt; e++) {
        int j = g_csr[start + e];
        float w = g_dinv_n[j];
        if (act) {
            const float4 v = *(const float4*)(g_u + (size_t)j * D + col);
            a.x = fmaf(w, v.x, a.x); a.y = fmaf(w, v.y, a.y);
            a.z = fmaf(w, v.z, a.z); a.w = fmaf(w, v.w, a.w);
        }
    }

    float v0 = 0.f, v1 = 0.f, v2 = 0.f, v3 = 0.f;
    if (act) {
        const float4 r = *(const float4*)(g_r + (size_t)node * D + col);
        v0 = fmaxf(fmaf(di, a.x, r.x), 0.f);
        v1 = fmaxf(fmaf(di, a.y, r.y), 0.f);
        v2 = fmaxf(fmaf(di, a.z, r.z), 0.f);
        v3 = fmaxf(fmaf(di, a.w, r.w), 0.f);
    }
    __syncthreads();
    if (s_same) {
        if (act) {
            atomicAdd(&sacc[col],     v0);
            atomicAdd(&sacc[col + 1], v1);
            atomicAdd(&sacc[col + 2], v2);
            atomicAdd(&sacc[col + 3], v3);
        }
        __syncthreads();
        if (threadIdx.x < D)
            atomicAdd(&g_pool[(size_t)s_b0 * D + threadIdx.x], sacc[threadIdx.x]);
    } else {
        if (act) {
            float* p = g_pool + (size_t)batch[node] * D + col;
            atomicAdd(&p[0], v0);
            atomicAdd(&p[1], v1);
            atomicAdd(&p[2], v2);
            atomicAdd(&p[3], v3);
        }
    }
}

// ---------------- small MLP GEMM (row per block) ----------------
template <int K, int NC, bool RELU>
__global__ void mlp_gemm(const float* __restrict__ A, const float* __restrict__ W,
                         const float* __restrict__ b, float* __restrict__ C) {
    __shared__ float As[K];
    int r = blockIdx.x;
    for (int k = threadIdx.x; k < K; k += blockDim.x) As[k] = A[r * K + k];
    __syncthreads();
    for (int c = threadIdx.x; c < NC; c += blockDim.x) {
        float acc = b[c];
#pragma unroll 4
        for (int k = 0; k < K; k++) acc = fmaf(As[k], W[k * NC + c], acc);
        C[r * NC + c] = RELU ? fmaxf(acc, 0.f) : acc;
    }
}

// ---------------- host helper: real device address of a __device__ symbol ----------------
static float* symaddr(const void* sym) {
    void* p = nullptr;
    cudaGetSymbolAddress(&p, sym);
    return (float*)p;
}

// ---------------- launcher ----------------
extern "C" void kernel_launch(void* const* d_in, const int* in_sizes, int n_in,
                              void* d_out, int out_size) {
    const float* x       = (const float*)d_in[0];
    const int*   src     = (const int*)d_in[1];
    const int*   dst     = (const int*)d_in[2];
    const int*   batch   = (const int*)d_in[3];
    const float* W1      = (const float*)d_in[4];
    const float* b1      = (const float*)d_in[5];
    const float* W2      = (const float*)d_in[6];
    const float* b2      = (const float*)d_in[7];
    const float* gamma   = (const float*)d_in[8];
    const float* beta    = (const float*)d_in[9];
    const float* Wa_init = (const float*)d_in[10];
    const float* Wa_root = (const float*)d_in[11];
    const float* ba      = (const float*)d_in[12];
    const float* Wf1     = (const float*)d_in[13];
    const float* bf1     = (const float*)d_in[14];
    const float* Wf2     = (const float*)d_in[15];
    const float* bf2     = (const float*)d_in[16];
    const float* Wf3     = (const float*)d_in[17];
    const float* bf3     = (const float*)d_in[18];
    const float* Wf4     = (const float*)d_in[19];
    const float* bf4     = (const float*)d_in[20];
    float* out = (float*)d_out;

    float* p_t0   = symaddr(g_t0);
    float* p_h1   = symaddr(g_h1);
    float* p_t1   = symaddr(g_t1);
    float* p_h2   = symaddr(g_h2);
    float* p_u    = symaddr(g_u);
    float* p_r    = symaddr(g_r);
    float* p_Wu   = symaddr(g_Wu);
    float* p_bu   = symaddr(g_bu);
    float* p_Wr   = symaddr(g_Wr);
    float* p_br   = symaddr(g_br);
    float* p_pool = symaddr(g_pool);
    float* p_m1   = symaddr(g_m1);
    float* p_m2   = symaddr(g_m2);
    float* p_m3   = symaddr(g_m3);

    const int GB_N = (NN + 255) / 256;       // 391
    const int GB_E = (EE + 255) / 256;       // 6250
    const int GB_P = (NN + 7) / 8;           // 12500 (warp per node, 8/block)
    const int GB_G = (NN + 79) / 80;         // 1250 (gemm_rf blocks)

    // 1-3: init + graph build (first half)
    zero_kernel<<<GB_N, 256>>>();
    deg_kernel<<<GB_E, 256>>>(dst);
    scan1_kernel<<<SCAN_B, 256>>>();
    // 4: SGConv-1 GEMM (independent)  <- ncu profiles launch #4
    gemm_rf<K1, 64><<<GB_G, 256>>>(x, W1, nullptr, p_t0);
    // 5-6: graph build (second half)
    scan2_kernel<<<1, 512>>>();
    csrfill_kernel<<<GB_E, 256>>>(src, dst);

    // SGConv 1 propagation
    prop_self_kernel<<<GB_P, 256>>>(p_t0, b1, p_h1);

    // SGConv 2
    gemm_rf<D, 50><<<GB_G, 256>>>(p_h1, W2, nullptr, p_t1);
    prop_self_kernel<<<GB_P, 256>>>(p_t1, b2, p_h2);

    // BatchNorm stats + fold into ARMA weights
    bn_stats_kernel<<<GB_N, 128>>>();
    fold_kernel<<<1, 256>>>(gamma, beta, Wa_init, Wa_root, ba);

    // ARMA: u = h2 @ Wu + bu ; r = h2 @ Wr + br
    gemm_rf<D, 50><<<GB_G, 256>>>(p_h2, p_Wu, p_bu, p_u);
    gemm_rf<D, 50><<<GB_G, 256>>>(p_h2, p_Wr, p_br, p_r);

    // a = relu(prop_noself(u) + r), pooled by graph id (fused, block-pooled)
    arma_pool_kernel<<<GB_P, 256>>>(batch);

    // MLP head on [512, 100]
    mlp_gemm<100, 200, true><<<NG, 256>>>(p_pool, Wf1, bf1, p_m1);
    mlp_gemm<200, 300, true><<<NG, 256>>>(p_m1, Wf2, bf2, p_m2);
    mlp_gemm<300, 200, true><<<NG, 256>>>(p_m2, Wf3, bf3, p_m3);
    mlp_gemm<200, 1, false><<<NG, 32>>>(p_m3, Wf4, bf4, out);
}

// round 10
// speedup vs baseline: 1.3723x; 1.0565x over previous
#include <cuda_runtime.h>
#include <cuda_bf16.h>
#include <cstdint>

// ---------------- problem constants ----------------
#define NN 100000
#define EE 1600000
#define NG 512
#define D  100      // hidden dim
#define K1 128      // input feature dim
#define SCAN_B ((NN + 255) / 256)   // 391 scan blocks

// ---------------- device scratch (static globals: allocation-free) ----------------
__device__ int   g_deg[NN];
__device__ int   g_cursor[NN];
__device__ int   g_off[NN];
__device__ int   g_part[512];
__device__ int   g_csr[EE];
__device__ float g_dinv_s[NN];
__device__ float g_dinv_n[NN];
__device__ float g_t0[(size_t)NN * D];
__device__ float g_h1[(size_t)NN * D];
__device__ float g_t1[(size_t)NN * D];
__device__ float g_h2[(size_t)NN * D];
__device__ float g_u[(size_t)NN * D];     // ARMA propagated input
__device__ float g_r[(size_t)NN * D];     // ARMA root part
__device__ float g_sum[D];
__device__ float g_sumsq[D];
__device__ float g_Wur[D * 200];          // BN-folded [Wa_init | Wa_root]
__device__ float g_bur[200];
__device__ float g_pool[NG * D];
__device__ float g_m1[NG * 200];
__device__ float g_m2[NG * 300];
__device__ float g_m3[NG * 200];

// ---------------- init ----------------
__global__ void zero_kernel() {
    int i = blockIdx.x * blockDim.x + threadIdx.x;
    int stride = gridDim.x * blockDim.x;
    for (int k = i; k < NN; k += stride) { g_deg[k] = 0; g_cursor[k] = 0; }
    for (int k = i; k < NG * D; k += stride) g_pool[k] = 0.f;
    if (i < D) { g_sum[i] = 0.f; g_sumsq[i] = 0.f; }
}

// ---------------- graph-build kernels ----------------
__global__ void deg_kernel(const int* __restrict__ dst) {
    int e = blockIdx.x * blockDim.x + threadIdx.x;
    if (e < EE) atomicAdd(&g_deg[dst[e]], 1);
}

__global__ void scan1_kernel() {
    __shared__ int sh[256];
    int tid = threadIdx.x;
    int i = blockIdx.x * 256 + tid;
    int v = (i < NN) ? g_deg[i] : 0;
    sh[tid] = v;
    __syncthreads();
    for (int ofs = 1; ofs < 256; ofs <<= 1) {
        int t = (tid >= ofs) ? sh[tid - ofs] : 0;
        __syncthreads();
        sh[tid] += t;
        __syncthreads();
    }
    if (i < NN) {
        g_off[i] = sh[tid] - v;
        g_dinv_s[i] = rsqrtf((float)(v + 1));
        g_dinv_n[i] = (v > 0) ? rsqrtf((float)v) : 0.f;
    }
    if (tid == 255) g_part[blockIdx.x] = sh[255];
}

__global__ void scan2_kernel() {
    __shared__ int sh[512];
    int tid = threadIdx.x;
    int v = (tid < SCAN_B) ? g_part[tid] : 0;
    sh[tid] = v;
    __syncthreads();
    for (int ofs = 1; ofs < 512; ofs <<= 1) {
        int t = (tid >= ofs) ? sh[tid - ofs] : 0;
        __syncthreads();
        sh[tid] += t;
        __syncthreads();
    }
    g_part[tid] = sh[tid] - v;
}

__global__ void csrfill_kernel(const int* __restrict__ src, const int* __restrict__ dst) {
    int e = blockIdx.x * blockDim.x + threadIdx.x;
    if (e < EE) {
        int d = dst[e];
        int pos = g_off[d] + g_part[d >> 8] + atomicAdd(&g_cursor[d], 1);
        g_csr[pos] = src[e];
    }
}

// ---------------- register-tiled node GEMM:  C[n x 100] = A[n x K] @ W[K x 100] (+bias) ----------
// Block: 80 rows x 100 cols, 256 threads (250 active: 25 col-groups x 10 row-groups).
// launch_bounds(256,4): cap 64 regs -> 4 blocks/SM for latency hiding.
template <int K, int KC>
__global__ void __launch_bounds__(256, 4)
gemm_rf(const float* __restrict__ A, const float* __restrict__ W,
        const float* __restrict__ bias, float* __restrict__ C) {
    constexpr int ROWS = 80;
    constexpr int XP = 84;               // pad: 4-way-max STS conflicts, float4-aligned
    __shared__ __align__(16) float Xs[KC * XP];
    __shared__ __align__(16) float Ws[KC * D];
    int tid = threadIdx.x;
    int rowbase = blockIdx.x * ROWS;
    bool active = tid < 250;
    int cx = tid % 25;                   // col group: cols 4*cx .. 4*cx+3
    int ry = active ? (tid / 25) : 0;    // row group: rows 8*ry .. 8*ry+7

    float4 acc[8];
#pragma unroll
    for (int i = 0; i < 8; i++) acc[i] = make_float4(0.f, 0.f, 0.f, 0.f);

    for (int k0 = 0; k0 < K; k0 += KC) {
        // W chunk is contiguous [KC x 100] -> float4 copy
        for (int idx = tid; idx < KC * (D / 4); idx += 256)
            ((float4*)Ws)[idx] = ((const float4*)(W + (size_t)k0 * D))[idx];
        for (int idx = tid; idx < ROWS * KC; idx += 256) {
            int r = idx / KC, k = idx % KC;
            int gr = rowbase + r;
            Xs[k * XP + r] = (gr < NN) ? A[(size_t)gr * K + k0 + k] : 0.f;
        }
        __syncthreads();

#pragma unroll 2
        for (int k = 0; k < KC; k++) {
            const float4 w  = *(const float4*)&Ws[k * D + cx * 4];
            const float4 xa = *(const float4*)&Xs[k * XP + ry * 8];
            const float4 xb = *(const float4*)&Xs[k * XP + ry * 8 + 4];
            float x[8] = {xa.x, xa.y, xa.z, xa.w, xb.x, xb.y, xb.z, xb.w};
#pragma unroll
            for (int i = 0; i < 8; i++) {
                acc[i].x = fmaf(x[i], w.x, acc[i].x);
                acc[i].y = fmaf(x[i], w.y, acc[i].y);
                acc[i].z = fmaf(x[i], w.z, acc[i].z);
                acc[i].w = fmaf(x[i], w.w, acc[i].w);
            }
        }
        __syncthreads();
    }

    if (active) {
        float4 bb = make_float4(0.f, 0.f, 0.f, 0.f);
        if (bias) bb = *(const float4*)&bias[cx * 4];
#pragma unroll
        for (int i = 0; i < 8; i++) {
            int gr = rowbase + ry * 8 + i;
            if (gr < NN) {
                float4 o;
                o.x = acc[i].x + bb.x; o.y = acc[i].y + bb.y;
                o.z = acc[i].z + bb.z; o.w = acc[i].w + bb.w;
                *(float4*)&C[(size_t)gr * D + cx * 4] = o;
            }
        }
    }
}

// ---------------- merged ARMA GEMM: [U | R] = A[n x 100] @ Wur[100 x 200] + bur ----------------
// Block: 40 rows x 200 cols, 256 threads (250 active: 50 col-groups x 5 row-groups).
template <int K, int KC>
__global__ void __launch_bounds__(256, 4)
gemm_ur(const float* __restrict__ A, const float* __restrict__ W,
        const float* __restrict__ bias, float* __restrict__ U, float* __restrict__ R) {
    constexpr int NC = 200;
    constexpr int ROWS = 40;
    constexpr int XP = 44;
    __shared__ __align__(16) float Xs[KC * XP];
    __shared__ __align__(16) float Ws[KC * NC];
    int tid = threadIdx.x;
    int rowbase = blockIdx.x * ROWS;
    bool active = tid < 250;
    int cx = tid % 50;                   // col group: cols 4*cx .. 4*cx+3
    int ry = active ? (tid / 50) : 0;    // row group: rows 8*ry .. 8*ry+7

    float4 acc[8];
#pragma unroll
    for (int i = 0; i < 8; i++) acc[i] = make_float4(0.f, 0.f, 0.f, 0.f);

    for (int k0 = 0; k0 < K; k0 += KC) {
        for (int idx = tid; idx < KC * (NC / 4); idx += 256)
            ((float4*)Ws)[idx] = ((const float4*)(W + (size_t)k0 * NC))[idx];
        for (int idx = tid; idx < ROWS * KC; idx += 256) {
            int r = idx / KC, k = idx % KC;
            int gr = rowbase + r;
            Xs[k * XP + r] = (gr < NN) ? A[(size_t)gr * K + k0 + k] : 0.f;
        }
        __syncthreads();

#pragma unroll 2
        for (int k = 0; k < KC; k++) {
            const float4 w  = *(const float4*)&Ws[k * NC + cx * 4];
            const float4 xa = *(const float4*)&Xs[k * XP + ry * 8];
            const float4 xb = *(const float4*)&Xs[k * XP + ry * 8 + 4];
            float x[8] = {xa.x, xa.y, xa.z, xa.w, xb.x, xb.y, xb.z, xb.w};
#pragma unroll
            for (int i = 0; i < 8; i++) {
                acc[i].x = fmaf(x[i], w.x, acc[i].x);
                acc[i].y = fmaf(x[i], w.y, acc[i].y);
                acc[i].z = fmaf(x[i], w.z, acc[i].z);
                acc[i].w = fmaf(x[i], w.w, acc[i].w);
            }
        }
        __syncthreads();
    }

    if (active) {
        int c = cx * 4;
        float4 bb = *(const float4*)&bias[c];
        bool isU = c < D;
        int cc = isU ? c : (c - D);
#pragma unroll
        for (int i = 0; i < 8; i++) {
            int gr = rowbase + ry * 8 + i;
            if (gr < NN) {
                float4 o;
                o.x = acc[i].x + bb.x; o.y = acc[i].y + bb.y;
                o.z = acc[i].z + bb.z; o.w = acc[i].w + bb.w;
                float* dstp = isU ? &U[(size_t)gr * D + cc] : &R[(size_t)gr * D + cc];
                *(float4*)dstp = o;
            }
        }
    }
}

// ---------------- GCN prop with self loops: warp/node, float4, uniform idx, unroll 4 ----------------
__global__ void prop_self_kernel(const float* __restrict__ T, const float* __restrict__ bias,
                                 float* __restrict__ out) {
    int node = blockIdx.x * 8 + (threadIdx.x >> 5);
    if (node >= NN) return;
    int lane = threadIdx.x & 31;
    int start = g_off[node] + g_part[node >> 8];
    int cnt = g_deg[node];
    float di = g_dinv_s[node];
    bool act = lane < 25;
    int col = lane * 4;
    float4 a = make_float4(0.f, 0.f, 0.f, 0.f);

    int e = 0;
    for (; e + 4 <= cnt; e += 4) {
        int j0 = g_csr[start + e];
        int j1 = g_csr[start + e + 1];
        int j2 = g_csr[start + e + 2];
        int j3 = g_csr[start + e + 3];
        float w0 = g_dinv_s[j0], w1 = g_dinv_s[j1];
        float w2 = g_dinv_s[j2], w3 = g_dinv_s[j3];
        if (act) {
            const float4 v0 = *(const float4*)(T + (size_t)j0 * D + col);
            const float4 v1 = *(const float4*)(T + (size_t)j1 * D + col);
            const float4 v2 = *(const float4*)(T + (size_t)j2 * D + col);
            const float4 v3 = *(const float4*)(T + (size_t)j3 * D + col);
            a.x = fmaf(w0, v0.x, a.x); a.y = fmaf(w0, v0.y, a.y);
            a.z = fmaf(w0, v0.z, a.z); a.w = fmaf(w0, v0.w, a.w);
            a.x = fmaf(w1, v1.x, a.x); a.y = fmaf(w1, v1.y, a.y);
            a.z = fmaf(w1, v1.z, a.z); a.w = fmaf(w1, v1.w, a.w);
            a.x = fmaf(w2, v2.x, a.x); a.y = fmaf(w2, v2.y, a.y);
            a.z = fmaf(w2, v2.z, a.z); a.w = fmaf(w2, v2.w, a.w);
            a.x = fmaf(w3, v3.x, a.x); a.y = fmaf(w3, v3.y, a.y);
            a.z = fmaf(w3, v3.z, a.z); a.w = fmaf(w3, v3.w, a.w);
        }
    }
    for (; e < cnt; e++) {
        int j = g_csr[start + e];
        float w = g_dinv_s[j];
        if (act) {
            const float4 v = *(const float4*)(T + (size_t)j * D + col);
            a.x = fmaf(w, v.x, a.x); a.y = fmaf(w, v.y, a.y);
            a.z = fmaf(w, v.z, a.z); a.w = fmaf(w, v.w, a.w);
        }
    }
    if (act) {
        const float4 v = *(const float4*)(T + (size_t)node * D + col);
        a.x = fmaf(di, v.x, a.x); a.y = fmaf(di, v.y, a.y);
        a.z = fmaf(di, v.z, a.z); a.w = fmaf(di, v.w, a.w);
        const float4 bb = *(const float4*)(bias + col);
        float4 o;
        o.x = fmaxf(fmaf(di, a.x, bb.x), 0.f);
        o.y = fmaxf(fmaf(di, a.y, bb.y), 0.f);
        o.z = fmaxf(fmaf(di, a.z, bb.z), 0.f);
        o.w = fmaxf(fmaf(di, a.w, bb.w), 0.f);
        *(float4*)(out + (size_t)node * D + col) = o;
    }
}

// ---------------- BatchNorm stats: register-column reduction, 1 atomic/block/col ----------------
__global__ void bn_stats_kernel() {
    int c = threadIdx.x;
    if (c >= D) return;
    int r0 = blockIdx.x * 256;
    int r1 = min(r0 + 256, NN);
    float s = 0.f, q = 0.f;
    for (int r = r0; r < r1; r++) {
        float v = g_h2[(size_t)r * D + c];
        s += v;
        q = fmaf(v, v, q);
    }
    atomicAdd(&g_sum[c], s);
    atomicAdd(&g_sumsq[c], q);
}

// ---------------- fold BatchNorm affine into ARMA weights (concat [Wu|Wr]) ----------------
// h = h2*s + t  =>  h@Wa = h2@(diag(s)Wa) + t@Wa
__global__ void fold_kernel(const float* __restrict__ gamma, const float* __restrict__ beta,
                            const float* __restrict__ Wa_init, const float* __restrict__ Wa_root,
                            const float* __restrict__ ba) {
    __shared__ float s[D], t[D];
    int tid = threadIdx.x;
    if (tid < D) {
        float mu = g_sum[tid] * (1.f / NN);
        float var = g_sumsq[tid] * (1.f / NN) - mu * mu;
        float rs = rsqrtf(var + 1e-5f);
        float sv = gamma[tid] * rs;
        s[tid] = sv;
        t[tid] = beta[tid] - mu * sv;
    }
    __syncthreads();
    for (int idx = tid; idx < D * 200; idx += blockDim.x) {
        int k = idx / 200, c = idx % 200;
        float w = (c < D) ? Wa_init[k * D + c] : Wa_root[k * D + (c - D)];
        g_Wur[idx] = s[k] * w;
    }
    for (int c = tid; c < 200; c += blockDim.x) {
        float acc;
        if (c < D) {
            acc = 0.f;
            for (int k = 0; k < D; k++) acc = fmaf(t[k], Wa_init[k * D + c], acc);
        } else {
            int cc = c - D;
            acc = ba[cc];
            for (int k = 0; k < D; k++) acc = fmaf(t[k], Wa_root[k * D + cc], acc);
        }
        g_bur[c] = acc;
    }
}

// ---------------- ARMA prop (no self loops) + root + relu + block-pooled scatter ----------------
__global__ void arma_pool_kernel(const int* __restrict__ batch) {
    __shared__ float sacc[D];
    __shared__ int s_b0, s_same;
    int wid = threadIdx.x >> 5;
    int lane = threadIdx.x & 31;
    int node = blockIdx.x * 8 + wid;

    if (threadIdx.x == 0) {
        int b0 = batch[blockIdx.x * 8];
        int b7 = batch[blockIdx.x * 8 + 7];
        s_b0 = b0;
        s_same = (b0 == b7) ? 1 : 0;
    }
    if (threadIdx.x < D) sacc[threadIdx.x] = 0.f;

    int start = g_off[node] + g_part[node >> 8];
    int cnt = g_deg[node];
    float di = g_dinv_n[node];
    bool act = lane < 25;
    int col = lane * 4;
    float4 a = make_float4(0.f, 0.f, 0.f, 0.f);

    int e = 0;
    for (; e + 4 <= cnt; e += 4) {
        int j0 = g_csr[start + e];
        int j1 = g_csr[start + e + 1];
        int j2 = g_csr[start + e + 2];
        int j3 = g_csr[start + e + 3];
        float w0 = g_dinv_n[j0], w1 = g_dinv_n[j1];
        float w2 = g_dinv_n[j2], w3 = g_dinv_n[j3];
        if (act) {
            const float4 v0 = *(const float4*)(g_u + (size_t)j0 * D + col);
            const float4 v1 = *(const float4*)(g_u + (size_t)j1 * D + col);
            const float4 v2 = *(const float4*)(g_u + (size_t)j2 * D + col);
            const float4 v3 = *(const float4*)(g_u + (size_t)j3 * D + col);
            a.x = fmaf(w0, v0.x, a.x); a.y = fmaf(w0, v0.y, a.y);
            a.z = fmaf(w0, v0.z, a.z); a.w = fmaf(w0, v0.w, a.w);
            a.x = fmaf(w1, v1.x, a.x); a.y = fmaf(w1, v1.y, a.y);
            a.z = fmaf(w1, v1.z, a.z); a.w = fmaf(w1, v1.w, a.w);
            a.x = fmaf(w2, v2.x, a.x); a.y = fmaf(w2, v2.y, a.y);
            a.z = fmaf(w2, v2.z, a.z); a.w = fmaf(w2, v2.w, a.w);
            a.x = fmaf(w3, v3.x, a.x); a.y = fmaf(w3, v3.y, a.y);
            a.z = fmaf(w3, v3.z, a.z); a.w = fmaf(w3, v3.w, a.w);
        }
    }
    for (; e < cnt; e++) {
        int j = g_csr[start + e];
        float w = g_dinv_n[j];
        if (act) {
            const float4 v = *(const float4*)(g_u + (size_t)j * D + col);
            a.x = fmaf(w, v.x, a.x); a.y = fmaf(w, v.y, a.y);
            a.z = fmaf(w, v.z, a.z); a.w = fmaf(w, v.w, a.w);
        }
    }

    float v0 = 0.f, v1 = 0.f, v2 = 0.f, v3 = 0.f;
    if (act) {
        const float4 r = *(const float4*)(g_r + (size_t)node * D + col);
        v0 = fmaxf(fmaf(di, a.x, r.x), 0.f);
        v1 = fmaxf(fmaf(di, a.y, r.y), 0.f);
        v2 = fmaxf(fmaf(di, a.z, r.z), 0.f);
        v3 = fmaxf(fmaf(di, a.w, r.w), 0.f);
    }
    __syncthreads();
    if (s_same) {
        if (act) {
            atomicAdd(&sacc[col],     v0);
            atomicAdd(&sacc[col + 1], v1);
            atomicAdd(&sacc[col + 2], v2);
            atomicAdd(&sacc[col + 3], v3);
        }
        __syncthreads();
        if (threadIdx.x < D)
            atomicAdd(&g_pool[(size_t)s_b0 * D + threadIdx.x], sacc[threadIdx.x]);
    } else {
        if (act) {
            float* p = g_pool + (size_t)batch[node] * D + col;
            atomicAdd(&p[0], v0);
            atomicAdd(&p[1], v1);
            atomicAdd(&p[2], v2);
            atomicAdd(&p[3], v3);
        }
    }
}

// ---------------- small MLP GEMM (row per block) ----------------
template <int K, int NC, bool RELU>
__global__ void mlp_gemm(const float* __restrict__ A, const float* __restrict__ W,
                         const float* __restrict__ b, float* __restrict__ C) {
    __shared__ float As[K];
    int r = blockIdx.x;
    for (int k = threadIdx.x; k < K; k += blockDim.x) As[k] = A[r * K + k];
    __syncthreads();
    for (int c = threadIdx.x; c < NC; c += blockDim.x) {
        float acc = b[c];
#pragma unroll 4
        for (int k = 0; k < K; k++) acc = fmaf(As[k], W[k * NC + c], acc);
        C[r * NC + c] = RELU ? fmaxf(acc, 0.f) : acc;
    }
}

// ---------------- host helper: real device address of a __device__ symbol ----------------
static float* symaddr(const void* sym) {
    void* p = nullptr;
    cudaGetSymbolAddress(&p, sym);
    return (float*)p;
}

// ---------------- launcher ----------------
extern "C" void kernel_launch(void* const* d_in, const int* in_sizes, int n_in,
                              void* d_out, int out_size) {
    const float* x       = (const float*)d_in[0];
    const int*   src     = (const int*)d_in[1];
    const int*   dst     = (const int*)d_in[2];
    const int*   batch   = (const int*)d_in[3];
    const float* W1      = (const float*)d_in[4];
    const float* b1      = (const float*)d_in[5];
    const float* W2      = (const float*)d_in[6];
    const float* b2      = (const float*)d_in[7];
    const float* gamma   = (const float*)d_in[8];
    const float* beta    = (const float*)d_in[9];
    const float* Wa_init = (const float*)d_in[10];
    const float* Wa_root = (const float*)d_in[11];
    const float* ba      = (const float*)d_in[12];
    const float* Wf1     = (const float*)d_in[13];
    const float* bf1     = (const float*)d_in[14];
    const float* Wf2     = (const float*)d_in[15];
    const float* bf2     = (const float*)d_in[16];
    const float* Wf3     = (const float*)d_in[17];
    const float* bf3     = (const float*)d_in[18];
    const float* Wf4     = (const float*)d_in[19];
    const float* bf4     = (const float*)d_in[20];
    float* out = (float*)d_out;

    float* p_t0   = symaddr(g_t0);
    float* p_h1   = symaddr(g_h1);
    float* p_t1   = symaddr(g_t1);
    float* p_h2   = symaddr(g_h2);
    float* p_u    = symaddr(g_u);
    float* p_r    = symaddr(g_r);
    float* p_Wur  = symaddr(g_Wur);
    float* p_bur  = symaddr(g_bur);
    float* p_pool = symaddr(g_pool);
    float* p_m1   = symaddr(g_m1);
    float* p_m2   = symaddr(g_m2);
    float* p_m3   = symaddr(g_m3);

    const int GB_N = (NN + 255) / 256;       // 391
    const int GB_E = (EE + 255) / 256;       // 6250
    const int GB_P = (NN + 7) / 8;           // 12500 (warp per node, 8/block)
    const int GB_G = (NN + 79) / 80;         // 1250 (gemm_rf blocks)
    const int GB_U = (NN + 39) / 40;         // 2500 (gemm_ur blocks)

    // 1-3: init + graph build (first half)
    zero_kernel<<<GB_N, 256>>>();
    deg_kernel<<<GB_E, 256>>>(dst);
    scan1_kernel<<<SCAN_B, 256>>>();
    // 4: SGConv-1 GEMM (independent)  <- ncu profiles launch #4
    gemm_rf<K1, 64><<<GB_G, 256>>>(x, W1, nullptr, p_t0);
    // 5-6: graph build (second half)
    scan2_kernel<<<1, 512>>>();
    csrfill_kernel<<<GB_E, 256>>>(src, dst);

    // SGConv 1 propagation
    prop_self_kernel<<<GB_P, 256>>>(p_t0, b1, p_h1);

    // SGConv 2
    gemm_rf<D, 50><<<GB_G, 256>>>(p_h1, W2, nullptr, p_t1);
    prop_self_kernel<<<GB_P, 256>>>(p_t1, b2, p_h2);

    // BatchNorm stats + fold into ARMA weights
    bn_stats_kernel<<<GB_N, 128>>>();
    fold_kernel<<<1, 256>>>(gamma, beta, Wa_init, Wa_root, ba);

    // ARMA: [u | r] = h2 @ Wur + bur  (single merged GEMM)
    gemm_ur<D, 50><<<GB_U, 256>>>(p_h2, p_Wur, p_bur, p_u, p_r);

    // a = relu(prop_noself(u) + r), pooled by graph id (fused, block-pooled)
    arma_pool_kernel<<<GB_P, 256>>>(batch);

    // MLP head on [512, 100]
    mlp_gemm<100, 200, true><<<NG, 256>>>(p_pool, Wf1, bf1, p_m1);
    mlp_gemm<200, 300, true><<<NG, 256>>>(p_m1, Wf2, bf2, p_m2);
    mlp_gemm<300, 200, true><<<NG, 256>>>(p_m2, Wf3, bf3, p_m3);
    mlp_gemm<200, 1, false><<<NG, 32>>>(p_m3, Wf4, bf4, out);
}

// round 11
// speedup vs baseline: 1.5203x; 1.1079x over previous
#include <cuda_runtime.h>
#include <cuda_fp16.h>
#include <cstdint>

// ---------------- problem constants ----------------
#define NN 100000
#define EE 1600000
#define NG 512
#define D  100      // hidden dim
#define K1 128      // input feature dim
#define SCAN_B ((NN + 255) / 256)   // 391 scan blocks

// ---------------- device scratch (static globals: allocation-free) ----------------
__device__ int    g_deg[NN];
__device__ int    g_cursor[NN];
__device__ int    g_off[NN];
__device__ int    g_part[512];
__device__ int    g_csr[EE];
__device__ float  g_dinv_s[NN];
__device__ float  g_dinv_n[NN];
__device__ __half g_t0[(size_t)NN * D];   // gathered operands stored fp16
__device__ float  g_h1[(size_t)NN * D];
__device__ __half g_t1[(size_t)NN * D];
__device__ float  g_h2[(size_t)NN * D];
__device__ __half g_u[(size_t)NN * D];    // ARMA propagated input (gathered)
__device__ float  g_r[(size_t)NN * D];    // ARMA root part (node-local)
__device__ float  g_sum[D];
__device__ float  g_sumsq[D];
__device__ float  g_Wur[D * 200];         // BN-folded [Wa_init | Wa_root]
__device__ float  g_bur[200];
__device__ float  g_pool[NG * D];
__device__ float  g_m1[NG * 200];
__device__ float  g_m2[NG * 300];
__device__ float  g_m3[NG * 200];

// ---------------- init ----------------
__global__ void zero_kernel() {
    int i = blockIdx.x * blockDim.x + threadIdx.x;
    int stride = gridDim.x * blockDim.x;
    for (int k = i; k < NN; k += stride) { g_deg[k] = 0; g_cursor[k] = 0; }
    for (int k = i; k < NG * D; k += stride) g_pool[k] = 0.f;
    if (i < D) { g_sum[i] = 0.f; g_sumsq[i] = 0.f; }
}

// ---------------- graph-build kernels ----------------
__global__ void deg_kernel(const int* __restrict__ dst) {
    int e = blockIdx.x * blockDim.x + threadIdx.x;
    if (e < EE) atomicAdd(&g_deg[dst[e]], 1);
}

__global__ void scan1_kernel() {
    __shared__ int sh[256];
    int tid = threadIdx.x;
    int i = blockIdx.x * 256 + tid;
    int v = (i < NN) ? g_deg[i] : 0;
    sh[tid] = v;
    __syncthreads();
    for (int ofs = 1; ofs < 256; ofs <<= 1) {
        int t = (tid >= ofs) ? sh[tid - ofs] : 0;
        __syncthreads();
        sh[tid] += t;
        __syncthreads();
    }
    if (i < NN) {
        g_off[i] = sh[tid] - v;
        g_dinv_s[i] = rsqrtf((float)(v + 1));
        g_dinv_n[i] = (v > 0) ? rsqrtf((float)v) : 0.f;
    }
    if (tid == 255) g_part[blockIdx.x] = sh[255];
}

__global__ void scan2_kernel() {
    __shared__ int sh[512];
    int tid = threadIdx.x;
    int v = (tid < SCAN_B) ? g_part[tid] : 0;
    sh[tid] = v;
    __syncthreads();
    for (int ofs = 1; ofs < 512; ofs <<= 1) {
        int t = (tid >= ofs) ? sh[tid - ofs] : 0;
        __syncthreads();
        sh[tid] += t;
        __syncthreads();
    }
    g_part[tid] = sh[tid] - v;
}

__global__ void csrfill_kernel(const int* __restrict__ src, const int* __restrict__ dst) {
    int e = blockIdx.x * blockDim.x + threadIdx.x;
    if (e < EE) {
        int d = dst[e];
        int pos = g_off[d] + g_part[d >> 8] + atomicAdd(&g_cursor[d], 1);
        g_csr[pos] = src[e];
    }
}

// ---------------- fp16 pack/unpack helpers ----------------
__device__ __forceinline__ void store_half4(__half* p, float a, float b, float c, float d) {
    __half2 h0 = __floats2half2_rn(a, b);
    __half2 h1 = __floats2half2_rn(c, d);
    uint2 pk;
    pk.x = *(unsigned*)&h0;
    pk.y = *(unsigned*)&h1;
    *(uint2*)p = pk;
}
__device__ __forceinline__ float4 load_half4(const __half* p) {
    uint2 pk = *(const uint2*)p;
    float2 f0 = __half22float2(*(__half2*)&pk.x);
    float2 f1 = __half22float2(*(__half2*)&pk.y);
    return make_float4(f0.x, f0.y, f1.x, f1.y);
}

// ---------------- register-tiled node GEMM:  C[n x 100] = A[n x K] @ W[K x 100] (+bias) ----------
// Block: 80 rows x 100 cols, 256 threads (250 active: 25 col-groups x 10 row-groups).
// HALF_OUT: write fp16 (for gathered operands).
template <int K, int KC, bool HALF_OUT>
__global__ void __launch_bounds__(256, 4)
gemm_rf(const float* __restrict__ A, const float* __restrict__ W,
        const float* __restrict__ bias, void* __restrict__ Cv) {
    constexpr int ROWS = 80;
    constexpr int XP = 84;
    __shared__ __align__(16) float Xs[KC * XP];
    __shared__ __align__(16) float Ws[KC * D];
    int tid = threadIdx.x;
    int rowbase = blockIdx.x * ROWS;
    bool active = tid < 250;
    int cx = tid % 25;
    int ry = active ? (tid / 25) : 0;

    float4 acc[8];
#pragma unroll
    for (int i = 0; i < 8; i++) acc[i] = make_float4(0.f, 0.f, 0.f, 0.f);

    for (int k0 = 0; k0 < K; k0 += KC) {
        for (int idx = tid; idx < KC * (D / 4); idx += 256)
            ((float4*)Ws)[idx] = ((const float4*)(W + (size_t)k0 * D))[idx];
        for (int idx = tid; idx < ROWS * KC; idx += 256) {
            int r = idx / KC, k = idx % KC;
            int gr = rowbase + r;
            Xs[k * XP + r] = (gr < NN) ? A[(size_t)gr * K + k0 + k] : 0.f;
        }
        __syncthreads();

#pragma unroll 2
        for (int k = 0; k < KC; k++) {
            const float4 w  = *(const float4*)&Ws[k * D + cx * 4];
            const float4 xa = *(const float4*)&Xs[k * XP + ry * 8];
            const float4 xb = *(const float4*)&Xs[k * XP + ry * 8 + 4];
            float x[8] = {xa.x, xa.y, xa.z, xa.w, xb.x, xb.y, xb.z, xb.w};
#pragma unroll
            for (int i = 0; i < 8; i++) {
                acc[i].x = fmaf(x[i], w.x, acc[i].x);
                acc[i].y = fmaf(x[i], w.y, acc[i].y);
                acc[i].z = fmaf(x[i], w.z, acc[i].z);
                acc[i].w = fmaf(x[i], w.w, acc[i].w);
            }
        }
        __syncthreads();
    }

    if (active) {
        float4 bb = make_float4(0.f, 0.f, 0.f, 0.f);
        if (bias) bb = *(const float4*)&bias[cx * 4];
#pragma unroll
        for (int i = 0; i < 8; i++) {
            int gr = rowbase + ry * 8 + i;
            if (gr < NN) {
                float ox = acc[i].x + bb.x, oy = acc[i].y + bb.y;
                float oz = acc[i].z + bb.z, ow = acc[i].w + bb.w;
                if (HALF_OUT) {
                    store_half4((__half*)Cv + (size_t)gr * D + cx * 4, ox, oy, oz, ow);
                } else {
                    *(float4*)((float*)Cv + (size_t)gr * D + cx * 4) =
                        make_float4(ox, oy, oz, ow);
                }
            }
        }
    }
}

// ---------------- merged ARMA GEMM: [U | R] = A[n x 100] @ Wur[100 x 200] + bur ----------------
// U written fp16 (gathered later), R written fp32 (node-local).
template <int K, int KC>
__global__ void __launch_bounds__(256, 4)
gemm_ur(const float* __restrict__ A, const float* __restrict__ W,
        const float* __restrict__ bias, __half* __restrict__ U, float* __restrict__ R) {
    constexpr int NC = 200;
    constexpr int ROWS = 40;
    constexpr int XP = 44;
    __shared__ __align__(16) float Xs[KC * XP];
    __shared__ __align__(16) float Ws[KC * NC];
    int tid = threadIdx.x;
    int rowbase = blockIdx.x * ROWS;
    bool active = tid < 250;
    int cx = tid % 50;
    int ry = active ? (tid / 50) : 0;

    float4 acc[8];
#pragma unroll
    for (int i = 0; i < 8; i++) acc[i] = make_float4(0.f, 0.f, 0.f, 0.f);

    for (int k0 = 0; k0 < K; k0 += KC) {
        for (int idx = tid; idx < KC * (NC / 4); idx += 256)
            ((float4*)Ws)[idx] = ((const float4*)(W + (size_t)k0 * NC))[idx];
        for (int idx = tid; idx < ROWS * KC; idx += 256) {
            int r = idx / KC, k = idx % KC;
            int gr = rowbase + r;
            Xs[k * XP + r] = (gr < NN) ? A[(size_t)gr * K + k0 + k] : 0.f;
        }
        __syncthreads();

#pragma unroll 2
        for (int k = 0; k < KC; k++) {
            const float4 w  = *(const float4*)&Ws[k * NC + cx * 4];
            const float4 xa = *(const float4*)&Xs[k * XP + ry * 8];
            const float4 xb = *(const float4*)&Xs[k * XP + ry * 8 + 4];
            float x[8] = {xa.x, xa.y, xa.z, xa.w, xb.x, xb.y, xb.z, xb.w};
#pragma unroll
            for (int i = 0; i < 8; i++) {
                acc[i].x = fmaf(x[i], w.x, acc[i].x);
                acc[i].y = fmaf(x[i], w.y, acc[i].y);
                acc[i].z = fmaf(x[i], w.z, acc[i].z);
                acc[i].w = fmaf(x[i], w.w, acc[i].w);
            }
        }
        __syncthreads();
    }

    if (active) {
        int c = cx * 4;
        float4 bb = *(const float4*)&bias[c];
        bool isU = c < D;
        int cc = isU ? c : (c - D);
#pragma unroll
        for (int i = 0; i < 8; i++) {
            int gr = rowbase + ry * 8 + i;
            if (gr < NN) {
                float ox = acc[i].x + bb.x, oy = acc[i].y + bb.y;
                float oz = acc[i].z + bb.z, ow = acc[i].w + bb.w;
                if (isU) store_half4(U + (size_t)gr * D + cc, ox, oy, oz, ow);
                else *(float4*)&R[(size_t)gr * D + cc] = make_float4(ox, oy, oz, ow);
            }
        }
    }
}

// ---------------- GCN prop with self loops: warp/node, fp16 gather, unroll 4 ----------------
__global__ void prop_self_kernel(const __half* __restrict__ T, const float* __restrict__ bias,
                                 float* __restrict__ out) {
    int node = blockIdx.x * 8 + (threadIdx.x >> 5);
    if (node >= NN) return;
    int lane = threadIdx.x & 31;
    int start = g_off[node] + g_part[node >> 8];
    int cnt = g_deg[node];
    float di = g_dinv_s[node];
    bool act = lane < 25;
    int col = lane * 4;
    float4 a = make_float4(0.f, 0.f, 0.f, 0.f);

    int e = 0;
    for (; e + 4 <= cnt; e += 4) {
        int j0 = g_csr[start + e];
        int j1 = g_csr[start + e + 1];
        int j2 = g_csr[start + e + 2];
        int j3 = g_csr[start + e + 3];
        float w0 = g_dinv_s[j0], w1 = g_dinv_s[j1];
        float w2 = g_dinv_s[j2], w3 = g_dinv_s[j3];
        if (act) {
            const float4 v0 = load_half4(T + (size_t)j0 * D + col);
            const float4 v1 = load_half4(T + (size_t)j1 * D + col);
            const float4 v2 = load_half4(T + (size_t)j2 * D + col);
            const float4 v3 = load_half4(T + (size_t)j3 * D + col);
            a.x = fmaf(w0, v0.x, a.x); a.y = fmaf(w0, v0.y, a.y);
            a.z = fmaf(w0, v0.z, a.z); a.w = fmaf(w0, v0.w, a.w);
            a.x = fmaf(w1, v1.x, a.x); a.y = fmaf(w1, v1.y, a.y);
            a.z = fmaf(w1, v1.z, a.z); a.w = fmaf(w1, v1.w, a.w);
            a.x = fmaf(w2, v2.x, a.x); a.y = fmaf(w2, v2.y, a.y);
            a.z = fmaf(w2, v2.z, a.z); a.w = fmaf(w2, v2.w, a.w);
            a.x = fmaf(w3, v3.x, a.x); a.y = fmaf(w3, v3.y, a.y);
            a.z = fmaf(w3, v3.z, a.z); a.w = fmaf(w3, v3.w, a.w);
        }
    }
    for (; e < cnt; e++) {
        int j = g_csr[start + e];
        float w = g_dinv_s[j];
        if (act) {
            const float4 v = load_half4(T + (size_t)j * D + col);
            a.x = fmaf(w, v.x, a.x); a.y = fmaf(w, v.y, a.y);
            a.z = fmaf(w, v.z, a.z); a.w = fmaf(w, v.w, a.w);
        }
    }
    if (act) {
        const float4 v = load_half4(T + (size_t)node * D + col);
        a.x = fmaf(di, v.x, a.x); a.y = fmaf(di, v.y, a.y);
        a.z = fmaf(di, v.z, a.z); a.w = fmaf(di, v.w, a.w);
        const float4 bb = *(const float4*)(bias + col);
        float4 o;
        o.x = fmaxf(fmaf(di, a.x, bb.x), 0.f);
        o.y = fmaxf(fmaf(di, a.y, bb.y), 0.f);
        o.z = fmaxf(fmaf(di, a.z, bb.z), 0.f);
        o.w = fmaxf(fmaf(di, a.w, bb.w), 0.f);
        *(float4*)(out + (size_t)node * D + col) = o;
    }
}

// ---------------- BatchNorm stats: register-column reduction, 1 atomic/block/col ----------------
__global__ void bn_stats_kernel() {
    int c = threadIdx.x;
    if (c >= D) return;
    int r0 = blockIdx.x * 256;
    int r1 = min(r0 + 256, NN);
    float s = 0.f, q = 0.f;
    for (int r = r0; r < r1; r++) {
        float v = g_h2[(size_t)r * D + c];
        s += v;
        q = fmaf(v, v, q);
    }
    atomicAdd(&g_sum[c], s);
    atomicAdd(&g_sumsq[c], q);
}

// ---------------- fold BatchNorm affine into ARMA weights (concat [Wu|Wr]) ----------------
__global__ void fold_kernel(const float* __restrict__ gamma, const float* __restrict__ beta,
                            const float* __restrict__ Wa_init, const float* __restrict__ Wa_root,
                            const float* __restrict__ ba) {
    __shared__ float s[D], t[D];
    int tid = threadIdx.x;
    if (tid < D) {
        float mu = g_sum[tid] * (1.f / NN);
        float var = g_sumsq[tid] * (1.f / NN) - mu * mu;
        float rs = rsqrtf(var + 1e-5f);
        float sv = gamma[tid] * rs;
        s[tid] = sv;
        t[tid] = beta[tid] - mu * sv;
    }
    __syncthreads();
    for (int idx = tid; idx < D * 200; idx += blockDim.x) {
        int k = idx / 200, c = idx % 200;
        float w = (c < D) ? Wa_init[k * D + c] : Wa_root[k * D + (c - D)];
        g_Wur[idx] = s[k] * w;
    }
    for (int c = tid; c < 200; c += blockDim.x) {
        float acc;
        if (c < D) {
            acc = 0.f;
            for (int k = 0; k < D; k++) acc = fmaf(t[k], Wa_init[k * D + c], acc);
        } else {
            int cc = c - D;
            acc = ba[cc];
            for (int k = 0; k < D; k++) acc = fmaf(t[k], Wa_root[k * D + cc], acc);
        }
        g_bur[c] = acc;
    }
}

// ---------------- ARMA prop (no self loops) + root + relu + block-pooled scatter ----------------
__global__ void arma_pool_kernel(const int* __restrict__ batch) {
    __shared__ float sacc[D];
    __shared__ int s_b0, s_same;
    int wid = threadIdx.x >> 5;
    int lane = threadIdx.x & 31;
    int node = blockIdx.x * 8 + wid;

    if (threadIdx.x == 0) {
        int b0 = batch[blockIdx.x * 8];
        int b7 = batch[blockIdx.x * 8 + 7];
        s_b0 = b0;
        s_same = (b0 == b7) ? 1 : 0;
    }
    if (threadIdx.x < D) sacc[threadIdx.x] = 0.f;

    int start = g_off[node] + g_part[node >> 8];
    int cnt = g_deg[node];
    float di = g_dinv_n[node];
    bool act = lane < 25;
    int col = lane * 4;
    float4 a = make_float4(0.f, 0.f, 0.f, 0.f);

    int e = 0;
    for (; e + 4 <= cnt; e += 4) {
        int j0 = g_csr[start + e];
        int j1 = g_csr[start + e + 1];
        int j2 = g_csr[start + e + 2];
        int j3 = g_csr[start + e + 3];
        float w0 = g_dinv_n[j0], w1 = g_dinv_n[j1];
        float w2 = g_dinv_n[j2], w3 = g_dinv_n[j3];
        if (act) {
            const float4 v0 = load_half4(g_u + (size_t)j0 * D + col);
            const float4 v1 = load_half4(g_u + (size_t)j1 * D + col);
            const float4 v2 = load_half4(g_u + (size_t)j2 * D + col);
            const float4 v3 = load_half4(g_u + (size_t)j3 * D + col);
            a.x = fmaf(w0, v0.x, a.x); a.y = fmaf(w0, v0.y, a.y);
            a.z = fmaf(w0, v0.z, a.z); a.w = fmaf(w0, v0.w, a.w);
            a.x = fmaf(w1, v1.x, a.x); a.y = fmaf(w1, v1.y, a.y);
            a.z = fmaf(w1, v1.z, a.z); a.w = fmaf(w1, v1.w, a.w);
            a.x = fmaf(w2, v2.x, a.x); a.y = fmaf(w2, v2.y, a.y);
            a.z = fmaf(w2, v2.z, a.z); a.w = fmaf(w2, v2.w, a.w);
            a.x = fmaf(w3, v3.x, a.x); a.y = fmaf(w3, v3.y, a.y);
            a.z = fmaf(w3, v3.z, a.z); a.w = fmaf(w3, v3.w, a.w);
        }
    }
    for (; e < cnt; e++) {
        int j = g_csr[start + e];
        float w = g_dinv_n[j];
        if (act) {
            const float4 v = load_half4(g_u + (size_t)j * D + col);
            a.x = fmaf(w, v.x, a.x); a.y = fmaf(w, v.y, a.y);
            a.z = fmaf(w, v.z, a.z); a.w = fmaf(w, v.w, a.w);
        }
    }

    float v0 = 0.f, v1 = 0.f, v2 = 0.f, v3 = 0.f;
    if (act) {
        const float4 r = *(const float4*)(g_r + (size_t)node * D + col);
        v0 = fmaxf(fmaf(di, a.x, r.x), 0.f);
        v1 = fmaxf(fmaf(di, a.y, r.y), 0.f);
        v2 = fmaxf(fmaf(di, a.z, r.z), 0.f);
        v3 = fmaxf(fmaf(di, a.w, r.w), 0.f);
    }
    __syncthreads();
    if (s_same) {
        if (act) {
            atomicAdd(&sacc[col],     v0);
            atomicAdd(&sacc[col + 1], v1);
            atomicAdd(&sacc[col + 2], v2);
            atomicAdd(&sacc[col + 3], v3);
        }
        __syncthreads();
        if (threadIdx.x < D)
            atomicAdd(&g_pool[(size_t)s_b0 * D + threadIdx.x], sacc[threadIdx.x]);
    } else {
        if (act) {
            float* p = g_pool + (size_t)batch[node] * D + col;
            atomicAdd(&p[0], v0);
            atomicAdd(&p[1], v1);
            atomicAdd(&p[2], v2);
            atomicAdd(&p[3], v3);
        }
    }
}

// ---------------- small MLP GEMM (row per block) ----------------
template <int K, int NC, bool RELU>
__global__ void mlp_gemm(const float* __restrict__ A, const float* __restrict__ W,
                         const float* __restrict__ b, float* __restrict__ C) {
    __shared__ float As[K];
    int r = blockIdx.x;
    for (int k = threadIdx.x; k < K; k += blockDim.x) As[k] = A[r * K + k];
    __syncthreads();
    for (int c = threadIdx.x; c < NC; c += blockDim.x) {
        float acc = b[c];
#pragma unroll 4
        for (int k = 0; k < K; k++) acc = fmaf(As[k], W[k * NC + c], acc);
        C[r * NC + c] = RELU ? fmaxf(acc, 0.f) : acc;
    }
}

// ---------------- host helper: real device address of a __device__ symbol ----------------
static void* symaddr_v(const void* sym) {
    void* p = nullptr;
    cudaGetSymbolAddress(&p, sym);
    return p;
}

// ---------------- launcher ----------------
extern "C" void kernel_launch(void* const* d_in, const int* in_sizes, int n_in,
                              void* d_out, int out_size) {
    const float* x       = (const float*)d_in[0];
    const int*   src     = (const int*)d_in[1];
    const int*   dst     = (const int*)d_in[2];
    const int*   batch   = (const int*)d_in[3];
    const float* W1      = (const float*)d_in[4];
    const float* b1      = (const float*)d_in[5];
    const float* W2      = (const float*)d_in[6];
    const float* b2      = (const float*)d_in[7];
    const float* gamma   = (const float*)d_in[8];
    const float* beta    = (const float*)d_in[9];
    const float* Wa_init = (const float*)d_in[10];
    const float* Wa_root = (const float*)d_in[11];
    const float* ba      = (const float*)d_in[12];
    const float* Wf1     = (const float*)d_in[13];
    const float* bf1     = (const float*)d_in[14];
    const float* Wf2     = (const float*)d_in[15];
    const float* bf2     = (const float*)d_in[16];
    const float* Wf3     = (const float*)d_in[17];
    const float* bf3     = (const float*)d_in[18];
    const float* Wf4     = (const float*)d_in[19];
    const float* bf4     = (const float*)d_in[20];
    float* out = (float*)d_out;

    __half* p_t0  = (__half*)symaddr_v(g_t0);
    float*  p_h1  = (float*)symaddr_v(g_h1);
    __half* p_t1  = (__half*)symaddr_v(g_t1);
    float*  p_h2  = (float*)symaddr_v(g_h2);
    __half* p_u   = (__half*)symaddr_v(g_u);
    float*  p_r   = (float*)symaddr_v(g_r);
    float*  p_Wur = (float*)symaddr_v(g_Wur);
    float*  p_bur = (float*)symaddr_v(g_bur);
    float*  p_pool= (float*)symaddr_v(g_pool);
    float*  p_m1  = (float*)symaddr_v(g_m1);
    float*  p_m2  = (float*)symaddr_v(g_m2);
    float*  p_m3  = (float*)symaddr_v(g_m3);

    const int GB_N = (NN + 255) / 256;       // 391
    const int GB_E = (EE + 255) / 256;       // 6250
    const int GB_P = (NN + 7) / 8;           // 12500 (warp per node, 8/block)
    const int GB_G = (NN + 79) / 80;         // 1250 (gemm_rf blocks)
    const int GB_U = (NN + 39) / 40;         // 2500 (gemm_ur blocks)

    // 1-3: init + graph build (first half)
    zero_kernel<<<GB_N, 256>>>();
    deg_kernel<<<GB_E, 256>>>(dst);
    scan1_kernel<<<SCAN_B, 256>>>();
    // 4: SGConv-1 GEMM (fp16 out)  <- ncu profiles launch #4
    gemm_rf<K1, 64, true><<<GB_G, 256>>>(x, W1, nullptr, p_t0);
    // 5-6: graph build (second half)
    scan2_kernel<<<1, 512>>>();
    csrfill_kernel<<<GB_E, 256>>>(src, dst);

    // SGConv 1 propagation (fp16 gather -> fp32 out)
    prop_self_kernel<<<GB_P, 256>>>(p_t0, b1, p_h1);

    // SGConv 2
    gemm_rf<D, 50, true><<<GB_G, 256>>>(p_h1, W2, nullptr, p_t1);
    prop_self_kernel<<<GB_P, 256>>>(p_t1, b2, p_h2);

    // BatchNorm stats + fold into ARMA weights
    bn_stats_kernel<<<GB_N, 128>>>();
    fold_kernel<<<1, 256>>>(gamma, beta, Wa_init, Wa_root, ba);

    // ARMA: [u | r] = h2 @ Wur + bur  (u fp16, r fp32)
    gemm_ur<D, 50><<<GB_U, 256>>>(p_h2, p_Wur, p_bur, p_u, p_r);

    // a = relu(prop_noself(u) + r), pooled by graph id (fused, block-pooled)
    arma_pool_kernel<<<GB_P, 256>>>(batch);

    // MLP head on [512, 100]
    mlp_gemm<100, 200, true><<<NG, 256>>>(p_pool, Wf1, bf1, p_m1);
    mlp_gemm<200, 300, true><<<NG, 256>>>(p_m1, Wf2, bf2, p_m2);
    mlp_gemm<300, 200, true><<<NG, 256>>>(p_m2, Wf3, bf3, p_m3);
    mlp_gemm<200, 1, false><<<NG, 32>>>(p_m3, Wf4, bf4, out);
}